// round 2
// baseline (speedup 1.0000x reference)
#include <cuda_runtime.h>
#include <math.h>

// ---------------- problem constants ----------------
constexpr int cD   = 15000;
constexpr int cE   = 300000;
constexpr int cDN  = 100;
constexpr int cDE  = 100;
constexpr int cDT  = 100;
constexpr int QF   = 201;   // DT+DN+1
constexpr int QFP  = 204;   // padded to mult of 4
constexpr int KVF  = 301;   // DT+DN+DE+1
constexpr int KVFP = 304;

constexpr int RB = 8;       // rows per block in GEMM kernels
constexpr int NT = 128;     // threads per block

// ---------------- scratch (device globals; no allocation allowed) ------------
__device__ float g_Kori [(size_t)cE * 128];
__device__ float g_KhE  [(size_t)cE * 128];
__device__ float g_Qori [(size_t)cD * 128];
__device__ float g_QhD  [(size_t)cD * 128];
__device__ float g_KhD  [(size_t)cD * 128];
__device__ float g_VhD  [(size_t)cD * 128];
__device__ float g_acc  [(size_t)cD * 128];
__device__ float g_ssum [cD];
__device__ float g_lself[cD];
__device__ int   g_mord [cD];
__device__ float g_logitE[cE];

__device__ float g_Wt_lq [QFP  * 128];
__device__ float g_Wt_lkv[KVFP * 128];
__device__ float g_Wt_q  [128 * 128];
__device__ float g_Wt_k  [128 * 128];
__device__ float g_Wt_v  [128 * 128];

// ---------------- helpers ----------------
__device__ __forceinline__ float warp_reduce_sum(float v) {
    #pragma unroll
    for (int o = 16; o > 0; o >>= 1) v += __shfl_xor_sync(0xffffffffu, v, o);
    return v;
}
__device__ __forceinline__ int f2ord(float f) {
    int i = __float_as_int(f);
    return (i >= 0) ? i : (i ^ 0x7fffffff);
}
__device__ __forceinline__ float ord2f(int i) {
    return __int_as_float((i >= 0) ? i : (i ^ 0x7fffffff));
}

// GEMM: 8 rows (in smem, stride KPAD) x Wt[KPAD][128] -> acc[8], col n = tid
template <int KPAD>
__device__ __forceinline__ void gemm8(const float* __restrict__ f,
                                      const float* __restrict__ Wt,
                                      const float* __restrict__ bias,
                                      int n, float* acc) {
    #pragma unroll
    for (int r = 0; r < RB; r++) acc[r] = 0.f;
    #pragma unroll 4
    for (int kk = 0; kk < KPAD; kk += 4) {
        float w0 = Wt[(kk + 0) * 128 + n];
        float w1 = Wt[(kk + 1) * 128 + n];
        float w2 = Wt[(kk + 2) * 128 + n];
        float w3 = Wt[(kk + 3) * 128 + n];
        #pragma unroll
        for (int r = 0; r < RB; r++) {
            float4 fv = *reinterpret_cast<const float4*>(f + r * KPAD + kk);
            acc[r] = fmaf(fv.x, w0, acc[r]);
            acc[r] = fmaf(fv.y, w1, acc[r]);
            acc[r] = fmaf(fv.z, w2, acc[r]);
            acc[r] = fmaf(fv.w, w3, acc[r]);
        }
    }
    float b = bias[n];
    #pragma unroll
    for (int r = 0; r < RB; r++) acc[r] += b;
}

// lorentz_linear epilogue: xbuf holds [RB][128] GEMM results; compute
// time = sigmoid(x0)*esc + 1.1,  scale = sqrt((t^2-1)/max(sum_{n>=1} x^2,1e-8))
__device__ __forceinline__ void lorentz_post_reduce(const float* xbuf, float esc,
                                                    float* time_sm, float* scale_sm,
                                                    int tid) {
    int warp = tid >> 5, lane = tid & 31;
    for (int r = warp; r < RB; r += 4) {
        float ss = 0.f;
        for (int c = lane; c < 128; c += 32) {
            float v = xbuf[r * 128 + c];
            if (c > 0) ss += v * v;
        }
        ss = warp_reduce_sum(ss);
        if (lane == 0) {
            float x0 = xbuf[r * 128];
            float t  = esc / (1.f + expf(-x0)) + 1.1f;
            time_sm[r]  = t;
            scale_sm[r] = sqrtf((t * t - 1.f) / fmaxf(ss, 1e-8f));
        }
    }
}

// ---------------- kernels ----------------

// Wt[k*128+n] = k < cols ? W[n*cols+k] : 0
__global__ void transpose_pad_kernel(const float* __restrict__ W, float* __restrict__ Wt,
                                     int cols, int colsPad) {
    int idx = blockIdx.x * blockDim.x + threadIdx.x;
    if (idx >= colsPad * 128) return;
    int k = idx / 128, n = idx % 128;
    Wt[idx] = (k < cols) ? W[n * cols + k] : 0.f;
}

// Q path: features [0, h(100), cos(te_b)(100)] -> expmap0 -> leaky -> GEMM(lq) -> post
__global__ void q_feat_kernel(const float* __restrict__ h, const float* __restrict__ te_b,
                              const float* __restrict__ Wt, const float* __restrict__ bias,
                              const float* __restrict__ log_s, float* __restrict__ out) {
    __shared__ float f[RB][QFP];
    __shared__ float time_sm[RB], scale_sm[RB];
    int r0 = blockIdx.x * RB, tid = threadIdx.x, n = tid;

    for (int idx = tid; idx < RB * QFP; idx += NT) {
        int r = idx / QFP, k = idx % QFP;
        int row = r0 + r;
        float v = 0.f;
        if (row < cD) {
            if (k >= 1 && k <= 100)       v = h[(size_t)row * cDN + (k - 1)];
            else if (k >= 101 && k <= 200) v = cosf(te_b[k - 101]);
        }
        f[r][k] = v;
    }
    __syncthreads();

    int warp = tid >> 5, lane = tid & 31;
    for (int r = warp; r < RB; r += 4) {
        float s = 0.f;
        for (int k = 1 + lane; k <= 200; k += 32) { float v = f[r][k]; s += v * v; }
        s = warp_reduce_sum(s);
        float nn = sqrtf(fmaxf(s, 1e-8f));
        if (lane == 0) { f[r][0] = coshf(nn); scale_sm[r] = sinhf(nn) / nn; }
    }
    __syncthreads();
    for (int idx = tid; idx < RB * QFP; idx += NT) {
        int r = idx / QFP, k = idx % QFP;
        if (k >= 1) {
            float v = f[r][k] * scale_sm[r];
            f[r][k] = (v >= 0.f) ? v : 0.2f * v;   // leaky relu (nonlin=True)
        }
    }
    __syncthreads();

    float acc[RB];
    gemm8<QFP>(&f[0][0], Wt, bias, n, acc);
    __syncthreads();
    float* xbuf = &f[0][0];
    #pragma unroll
    for (int r = 0; r < RB; r++) xbuf[r * 128 + n] = acc[r];
    __syncthreads();
    float esc = expf(*log_s);
    lorentz_post_reduce(xbuf, esc, time_sm, scale_sm, tid);
    __syncthreads();
    #pragma unroll
    for (int r = 0; r < RB; r++) {
        int row = r0 + r;
        if (row < cD) {
            float v = (n == 0) ? time_sm[r] : xbuf[r * 128 + n] * scale_sm[r];
            out[(size_t)row * 128 + n] = v;
        }
    }
}

// K path: features [0, h[D+e](100), ef(100), cos(dt*te_w+te_b)(100)]
__global__ void k_feat_kernel(const float* __restrict__ h, const float* __restrict__ ef,
                              const float* __restrict__ dt, const float* __restrict__ te_w,
                              const float* __restrict__ te_b,
                              const float* __restrict__ Wt, const float* __restrict__ bias,
                              const float* __restrict__ log_s, float* __restrict__ out) {
    __shared__ float f[RB][KVFP];
    __shared__ float time_sm[RB], scale_sm[RB];
    int e0 = blockIdx.x * RB, tid = threadIdx.x, n = tid;

    for (int idx = tid; idx < RB * KVFP; idx += NT) {
        int r = idx / KVFP, k = idx % KVFP;
        int e = e0 + r;
        float v = 0.f;
        if (e < cE) {
            if (k >= 1 && k <= 100)        v = h[(size_t)(cD + e) * cDN + (k - 1)];
            else if (k >= 101 && k <= 200) v = ef[(size_t)e * cDE + (k - 101)];
            else if (k >= 201 && k <= 300) {
                int j = k - 201;
                v = cosf(dt[e] * te_w[j] + te_b[j]);
            }
        }
        f[r][k] = v;
    }
    __syncthreads();

    int warp = tid >> 5, lane = tid & 31;
    for (int r = warp; r < RB; r += 4) {
        float s = 0.f;
        for (int k = 1 + lane; k <= 300; k += 32) { float v = f[r][k]; s += v * v; }
        s = warp_reduce_sum(s);
        float nn = sqrtf(fmaxf(s, 1e-8f));
        if (lane == 0) { f[r][0] = coshf(nn); scale_sm[r] = sinhf(nn) / nn; }
    }
    __syncthreads();
    for (int idx = tid; idx < RB * KVFP; idx += NT) {
        int r = idx / KVFP, k = idx % KVFP;
        if (k >= 1) {
            float v = f[r][k] * scale_sm[r];
            f[r][k] = (v >= 0.f) ? v : 0.2f * v;
        }
    }
    __syncthreads();

    float acc[RB];
    gemm8<KVFP>(&f[0][0], Wt, bias, n, acc);
    __syncthreads();
    float* xbuf = &f[0][0];
    #pragma unroll
    for (int r = 0; r < RB; r++) xbuf[r * 128 + n] = acc[r];
    __syncthreads();
    float esc = expf(*log_s);
    lorentz_post_reduce(xbuf, esc, time_sm, scale_sm, tid);
    __syncthreads();
    #pragma unroll
    for (int r = 0; r < RB; r++) {
        int e = e0 + r;
        if (e < cE) {
            float v = (n == 0) ? time_sm[r] : xbuf[r * 128 + n] * scale_sm[r];
            out[(size_t)e * 128 + n] = v;
        }
    }
}

// generic lorentz_linear 128->128 (no nonlin)
__global__ void ll128_kernel(const float* __restrict__ in, const float* __restrict__ Wt,
                             const float* __restrict__ bias, const float* __restrict__ log_s,
                             float* __restrict__ out, int M) {
    __shared__ float f[RB][128];
    __shared__ float time_sm[RB], scale_sm[RB];
    int r0 = blockIdx.x * RB, tid = threadIdx.x, n = tid;
    for (int idx = tid; idx < RB * 128; idx += NT) {
        int r = idx >> 7, k = idx & 127;
        int row = r0 + r;
        f[r][k] = (row < M) ? in[(size_t)row * 128 + k] : 0.f;
    }
    __syncthreads();
    float acc[RB];
    gemm8<128>(&f[0][0], Wt, bias, n, acc);
    __syncthreads();
    float* xbuf = &f[0][0];
    #pragma unroll
    for (int r = 0; r < RB; r++) xbuf[r * 128 + n] = acc[r];
    __syncthreads();
    float esc = expf(*log_s);
    lorentz_post_reduce(xbuf, esc, time_sm, scale_sm, tid);
    __syncthreads();
    #pragma unroll
    for (int r = 0; r < RB; r++) {
        int row = r0 + r;
        if (row < M) {
            float v = (n == 0) ? time_sm[r] : xbuf[r * 128 + n] * scale_sm[r];
            out[(size_t)row * 128 + n] = v;
        }
    }
}

// Kh for edges + fused edge logits + segment max (atomicMax on ordered ints)
__global__ void kh_logit_kernel(const float* __restrict__ in, const float* __restrict__ Wt,
                                const float* __restrict__ bias, const float* __restrict__ log_s,
                                const float* __restrict__ QhD, const int* __restrict__ edge_dst,
                                const float* __restrict__ att,
                                float* __restrict__ KhE, float* __restrict__ logitE,
                                int* __restrict__ mord) {
    __shared__ float f[RB][128];
    __shared__ float time_sm[RB], scale_sm[RB];
    int e0 = blockIdx.x * RB, tid = threadIdx.x, n = tid;
    for (int idx = tid; idx < RB * 128; idx += NT) {
        int r = idx >> 7, k = idx & 127;
        int e = e0 + r;
        f[r][k] = (e < cE) ? in[(size_t)e * 128 + k] : 0.f;
    }
    __syncthreads();
    float acc[RB];
    gemm8<128>(&f[0][0], Wt, bias, n, acc);
    __syncthreads();
    float* xbuf = &f[0][0];
    #pragma unroll
    for (int r = 0; r < RB; r++) xbuf[r * 128 + n] = acc[r];
    __syncthreads();
    float esc = expf(*log_s);
    lorentz_post_reduce(xbuf, esc, time_sm, scale_sm, tid);
    __syncthreads();
    #pragma unroll
    for (int r = 0; r < RB; r++) {
        int e = e0 + r;
        if (e < cE) {
            float v = (n == 0) ? time_sm[r] : xbuf[r * 128 + n] * scale_sm[r];
            KhE[(size_t)e * 128 + n] = v;
        }
    }
    int warp = tid >> 5, lane = tid & 31;
    float attv = *att;
    for (int r = warp; r < RB; r += 4) {
        int e = e0 + r;
        if (e >= cE) continue;
        int dst = edge_dst[e];
        float s = 0.f;
        for (int c = lane; c < 128; c += 32) {
            float kv = (c == 0) ? time_sm[r] : xbuf[r * 128 + c] * scale_sm[r];
            float qv = QhD[(size_t)dst * 128 + c];
            s += (c == 0) ? -kv * qv : kv * qv;   // minkowski inner
        }
        s = warp_reduce_sum(s);
        if (lane == 0) {
            float lg = (2.f + 2.f * s) / attv;
            logitE[e] = lg;
            atomicMax(&mord[dst], f2ord(lg));
        }
    }
}

// self-loop logits (one warp per node); also initializes segment max
__global__ void self_logit_kernel(const float* __restrict__ QhD, const float* __restrict__ KhD,
                                  const float* __restrict__ att,
                                  float* __restrict__ lself, int* __restrict__ mord) {
    int d = blockIdx.x * 4 + (threadIdx.x >> 5);
    int lane = threadIdx.x & 31;
    if (d >= cD) return;
    float s = 0.f;
    #pragma unroll
    for (int i = 0; i < 4; i++) {
        int c = lane + 32 * i;
        float q = QhD[(size_t)d * 128 + c];
        float k = KhD[(size_t)d * 128 + c];
        s += (c == 0) ? -q * k : q * k;
    }
    s = warp_reduce_sum(s);
    if (lane == 0) {
        float lg = (2.f + 2.f * s) / (*att);
        lself[d] = lg;
        mord[d]  = f2ord(lg);
    }
}

// initialize accumulator with self term (fresh assignment: graph-replay safe)
__global__ void init_acc_kernel(const float* __restrict__ VhD, const float* __restrict__ lself,
                                const int* __restrict__ mord,
                                float* __restrict__ acc, float* __restrict__ ssum) {
    int d = blockIdx.x, n = threadIdx.x;
    float w = expf(lself[d] - ord2f(mord[d]));
    acc[(size_t)d * 128 + n] = VhD[(size_t)d * 128 + n] * w;
    if (n == 0) ssum[d] = w;
}

// per-edge: Vh = lorentz_linear(KhE, wv) computed on the fly, then weighted atomic scatter
__global__ void edge_agg_kernel(const float* __restrict__ KhE, const float* __restrict__ Wt,
                                const float* __restrict__ bias, const float* __restrict__ log_s,
                                const float* __restrict__ logitE, const int* __restrict__ mord,
                                const int* __restrict__ edge_dst,
                                float* __restrict__ accg, float* __restrict__ ssum) {
    __shared__ float f[RB][128];
    __shared__ float time_sm[RB], scale_sm[RB], w_sm[RB];
    int e0 = blockIdx.x * RB, tid = threadIdx.x, n = tid;
    for (int idx = tid; idx < RB * 128; idx += NT) {
        int r = idx >> 7, k = idx & 127;
        int e = e0 + r;
        f[r][k] = (e < cE) ? KhE[(size_t)e * 128 + k] : 0.f;
    }
    __syncthreads();
    float acc[RB];
    gemm8<128>(&f[0][0], Wt, bias, n, acc);
    __syncthreads();
    float* xbuf = &f[0][0];
    #pragma unroll
    for (int r = 0; r < RB; r++) xbuf[r * 128 + n] = acc[r];
    __syncthreads();
    float esc = expf(*log_s);
    lorentz_post_reduce(xbuf, esc, time_sm, scale_sm, tid);
    if (tid < RB) {
        int e = e0 + tid;
        w_sm[tid] = 0.f;
        if (e < cE) {
            int dst = edge_dst[e];
            w_sm[tid] = expf(logitE[e] - ord2f(mord[dst]));
        }
    }
    __syncthreads();
    #pragma unroll
    for (int r = 0; r < RB; r++) {
        int e = e0 + r;
        if (e >= cE) continue;
        int dst = edge_dst[e];
        float v = (n == 0) ? time_sm[r] : xbuf[r * 128 + n] * scale_sm[r];
        atomicAdd(&accg[(size_t)dst * 128 + n], v * w_sm[r]);
        if (n == 0) atomicAdd(&ssum[dst], w_sm[r]);
    }
}

// finalize: rst = acc/ssum; normalize by Minkowski norm; logmap0 -> out
__global__ void finalize_kernel(const float* __restrict__ acc, const float* __restrict__ ssum,
                                float* __restrict__ out) {
    int d = blockIdx.x * 4 + (threadIdx.x >> 5);
    int lane = threadIdx.x & 31;
    if (d >= cD) return;
    float inv_s = 1.f / ssum[d];
    float rv[4];
    float sq = 0.f;
    #pragma unroll
    for (int i = 0; i < 4; i++) {
        int c = lane + 32 * i;
        float v = acc[(size_t)d * 128 + c] * inv_s;
        rv[i] = v;
        if (c != 0) sq += v * v;
    }
    sq = warp_reduce_sum(sq);
    float r0 = __shfl_sync(0xffffffffu, rv[0], 0);
    float neg_inner = r0 * r0 - sq;                 // -minkowski(rst,rst)
    float denom = sqrtf(fmaxf(fabsf(neg_inner), 1e-8f));
    float a = fmaxf(r0 / denom, 1.f + 1e-7f);
    float coef = acoshf(a) / sqrtf(fmaxf(a * a - 1.f, 1e-8f));
    #pragma unroll
    for (int i = 0; i < 4; i++) {
        int c = lane + 32 * i;
        out[(size_t)d * 128 + c] = (c == 0) ? 0.f : coef * (rv[i] / denom);
    }
}

// ---------------- launch ----------------
extern "C" void kernel_launch(void* const* d_in, const int* in_sizes, int n_in,
                              void* d_out, int out_size) {
    const float* h     = (const float*)d_in[0];
    const float* ef    = (const float*)d_in[1];
    const float* dt    = (const float*)d_in[2];
    const float* te_w  = (const float*)d_in[3];
    const float* te_b  = (const float*)d_in[4];
    const float* lq_W  = (const float*)d_in[5];
    const float* lq_b  = (const float*)d_in[6];
    const float* lq_s  = (const float*)d_in[7];
    const float* lkv_W = (const float*)d_in[8];
    const float* lkv_b = (const float*)d_in[9];
    const float* lkv_s = (const float*)d_in[10];
    const float* wq_W  = (const float*)d_in[11];
    const float* wq_b  = (const float*)d_in[12];
    const float* wq_s  = (const float*)d_in[13];
    const float* wk_W  = (const float*)d_in[14];
    const float* wk_b  = (const float*)d_in[15];
    const float* wk_s  = (const float*)d_in[16];
    const float* wv_W  = (const float*)d_in[17];
    const float* wv_b  = (const float*)d_in[18];
    const float* wv_s  = (const float*)d_in[19];
    const float* att   = (const float*)d_in[20];
    const int*   edst  = (const int*)d_in[21];
    float* out = (float*)d_out;

    float *Wt_lq, *Wt_lkv, *Wt_q, *Wt_k, *Wt_v;
    float *Kori, *KhE, *Qori, *QhD, *KhD, *VhD, *accb, *ssum, *lself, *logitE;
    int *mord;
    cudaGetSymbolAddress((void**)&Wt_lq,  g_Wt_lq);
    cudaGetSymbolAddress((void**)&Wt_lkv, g_Wt_lkv);
    cudaGetSymbolAddress((void**)&Wt_q,   g_Wt_q);
    cudaGetSymbolAddress((void**)&Wt_k,   g_Wt_k);
    cudaGetSymbolAddress((void**)&Wt_v,   g_Wt_v);
    cudaGetSymbolAddress((void**)&Kori,   g_Kori);
    cudaGetSymbolAddress((void**)&KhE,    g_KhE);
    cudaGetSymbolAddress((void**)&Qori,   g_Qori);
    cudaGetSymbolAddress((void**)&QhD,    g_QhD);
    cudaGetSymbolAddress((void**)&KhD,    g_KhD);
    cudaGetSymbolAddress((void**)&VhD,    g_VhD);
    cudaGetSymbolAddress((void**)&accb,   g_acc);
    cudaGetSymbolAddress((void**)&ssum,   g_ssum);
    cudaGetSymbolAddress((void**)&lself,  g_lself);
    cudaGetSymbolAddress((void**)&logitE, g_logitE);
    cudaGetSymbolAddress((void**)&mord,   g_mord);

    transpose_pad_kernel<<<(QFP * 128 + 255) / 256, 256>>>(lq_W, Wt_lq, QF, QFP);
    transpose_pad_kernel<<<(KVFP * 128 + 255) / 256, 256>>>(lkv_W, Wt_lkv, KVF, KVFP);
    transpose_pad_kernel<<<(128 * 128 + 255) / 256, 256>>>(wq_W, Wt_q, 128, 128);
    transpose_pad_kernel<<<(128 * 128 + 255) / 256, 256>>>(wk_W, Wt_k, 128, 128);
    transpose_pad_kernel<<<(128 * 128 + 255) / 256, 256>>>(wv_W, Wt_v, 128, 128);

    // node (D) path
    q_feat_kernel<<<(cD + RB - 1) / RB, NT>>>(h, te_b, Wt_lq, lq_b, lq_s, Qori);
    ll128_kernel<<<(cD + RB - 1) / RB, NT>>>(Qori, Wt_q, wq_b, wq_s, QhD, cD);
    ll128_kernel<<<(cD + RB - 1) / RB, NT>>>(Qori, Wt_k, wk_b, wk_s, KhD, cD);
    ll128_kernel<<<(cD + RB - 1) / RB, NT>>>(KhD,  Wt_v, wv_b, wv_s, VhD, cD);
    self_logit_kernel<<<(cD + 3) / 4, NT>>>(QhD, KhD, att, lself, mord);

    // edge (E) path
    k_feat_kernel<<<(cE + RB - 1) / RB, NT>>>(h, ef, dt, te_w, te_b, Wt_lkv, lkv_b, lkv_s, Kori);
    kh_logit_kernel<<<(cE + RB - 1) / RB, NT>>>(Kori, Wt_k, wk_b, wk_s, QhD, edst, att,
                                                KhE, logitE, mord);

    // softmax + aggregation
    init_acc_kernel<<<cD, NT>>>(VhD, lself, mord, accb, ssum);
    edge_agg_kernel<<<(cE + RB - 1) / RB, NT>>>(KhE, Wt_v, wv_b, wv_s, logitE, mord, edst,
                                                accb, ssum);
    finalize_kernel<<<(cD + 3) / 4, NT>>>(accb, ssum, out);
}

// round 5
// speedup vs baseline: 1.0472x; 1.0472x over previous
#include <cuda_runtime.h>
#include <math.h>
#include <stdint.h>

// ---------------- problem constants ----------------
constexpr int cD   = 15000;
constexpr int cE   = 300000;
constexpr int QF   = 201;   // DT+DN+1
constexpr int QFP  = 256;   // padded to 4 chunks of 64
constexpr int KVF  = 301;   // DT+DN+DE+1
constexpr int KVFP = 320;   // padded to 5 chunks of 64

// ---------------- scratch (device globals) ----------------
__device__ float g_QhD [(size_t)cD * 128];
__device__ float g_acc [(size_t)cD * 128];
__device__ float g_ssum[cD];
__device__ float g_Wt_lq [QFP  * 128];
__device__ float g_Wt_lkv[KVFP * 128];
__device__ float g_Wt_q  [128 * 128];
__device__ float g_Wt_k  [128 * 128];
__device__ float g_Wt_v  [128 * 128];

// ---------------- helpers ----------------
__device__ __forceinline__ float warp_reduce_sum(float v) {
    #pragma unroll
    for (int o = 16; o > 0; o >>= 1) v += __shfl_xor_sync(0xffffffffu, v, o);
    return v;
}
__device__ __forceinline__ float to_tf32(float x) {
    uint32_t u;
    asm("cvt.rna.tf32.f32 %0, %1;" : "=r"(u) : "f"(x));
    return __uint_as_float(u);
}
// exact split: x = hi + lo, hi/lo tf32-representable
__device__ __forceinline__ void split_tf32(float x, float& hi, float& lo) {
    hi = to_tf32(x);
    lo = to_tf32(x - hi);
}
__device__ __forceinline__ void mma_tf32(float* c, float a0, float a1, float a2, float a3,
                                         float b0, float b1) {
    asm volatile(
        "mma.sync.aligned.m16n8k8.row.col.f32.tf32.tf32.f32 "
        "{%0,%1,%2,%3}, {%4,%5,%6,%7}, {%8,%9}, {%0,%1,%2,%3};"
        : "+f"(c[0]), "+f"(c[1]), "+f"(c[2]), "+f"(c[3])
        : "r"(__float_as_uint(a0)), "r"(__float_as_uint(a1)),
          "r"(__float_as_uint(a2)), "r"(__float_as_uint(a3)),
          "r"(__float_as_uint(b0)), "r"(__float_as_uint(b1)));
}

// ---------------- smem layouts (explicit offsets; stage aliases dead buffers) ----
constexpr int ACT_F   = 128 * 132;          // stride 132 (==4 mod 32)
constexpr int BMAT_F  = 64 * 136;           // stride 136 (==8 mod 32)

// E kernel: [act | bmat | nsc | nco | w | dst];  stage aliases act
constexpr int E_BMAT = ACT_F;
constexpr int E_NSC  = E_BMAT + BMAT_F;
constexpr int E_NCO  = E_NSC + 128;
constexpr int E_W    = E_NCO + 128;
constexpr int E_DST  = E_W + 128;
constexpr int E_TOTAL_F = E_DST + 128;      // ~102.5 KB

// D kernel: [act | q | bmat | nsc | nco | w];  stage aliases q
constexpr int D_Q    = ACT_F;
constexpr int D_BMAT = D_Q + ACT_F;
constexpr int D_NSC  = D_BMAT + BMAT_F;
constexpr int D_NCO  = D_NSC + 128;
constexpr int D_W    = D_NCO + 128;
constexpr int D_TOTAL_F = D_W + 128;        // ~170 KB

// one K-chunk (64) of 3xTF32 mma accumulation. warp tile = 32 rows x 64 cols.
// A, B live in smem as full fp32; hi/lo splits done in registers.
__device__ __forceinline__ void mma_chunk(float (&c)[2][8][4], const float* sA, int ldA,
                                          const float* sB,
                                          int warpM, int warpN, int g, int tig) {
    #pragma unroll
    for (int kt = 0; kt < 8; kt++) {
        const int k0 = kt * 8;
        float ah[2][4], al[2][4];
        #pragma unroll
        for (int mt = 0; mt < 2; mt++) {
            const float* pr = sA + (warpM * 32 + mt * 16 + g) * ldA + k0 + tig;
            split_tf32(pr[0],            ah[mt][0], al[mt][0]);
            split_tf32(pr[8 * ldA],      ah[mt][1], al[mt][1]);
            split_tf32(pr[4],            ah[mt][2], al[mt][2]);
            split_tf32(pr[8 * ldA + 4],  ah[mt][3], al[mt][3]);
        }
        #pragma unroll
        for (int nt = 0; nt < 8; nt++) {
            int col = warpN * 64 + nt * 8 + g;
            float b0h, b0l, b1h, b1l;
            split_tf32(sB[(k0 + tig) * 136 + col],     b0h, b0l);
            split_tf32(sB[(k0 + tig + 4) * 136 + col], b1h, b1l);
            #pragma unroll
            for (int mt = 0; mt < 2; mt++) {
                // small terms first, big last (better rounding behavior)
                mma_tf32(c[mt][nt], al[mt][0], al[mt][1], al[mt][2], al[mt][3], b0h, b1h);
                mma_tf32(c[mt][nt], ah[mt][0], ah[mt][1], ah[mt][2], ah[mt][3], b0l, b1l);
                mma_tf32(c[mt][nt], ah[mt][0], ah[mt][1], ah[mt][2], ah[mt][3], b0h, b1h);
            }
        }
    }
}

__device__ __forceinline__ void zero_c(float (&c)[2][8][4]) {
    #pragma unroll
    for (int mt = 0; mt < 2; mt++)
        #pragma unroll
        for (int nt = 0; nt < 8; nt++)
            #pragma unroll
            for (int i = 0; i < 4; i++) c[mt][nt][i] = 0.f;
}

// stage 64x128 fp32 B chunk into sB
__device__ __forceinline__ void stage_B(float* sB, const float* Wsrc, int tid) {
    #pragma unroll
    for (int idx = tid; idx < 64 * 32; idx += 256) {
        int k = idx >> 5, n4 = (idx & 31) << 2;
        float4 v = *reinterpret_cast<const float4*>(Wsrc + k * 128 + n4);
        *reinterpret_cast<float4*>(sB + k * 136 + n4) = v;
    }
}

// write C regs + bias into buf[128][132]
__device__ __forceinline__ void epilogue_store(const float (&c)[2][8][4], float* buf,
                                               const float* __restrict__ bias,
                                               int warpM, int warpN, int g, int tig) {
    #pragma unroll
    for (int mt = 0; mt < 2; mt++) {
        int row = warpM * 32 + mt * 16 + g;
        #pragma unroll
        for (int nt = 0; nt < 8; nt++) {
            int col = warpN * 64 + nt * 8 + tig * 2;
            float b0 = bias[col], b1 = bias[col + 1];
            buf[row * 132 + col]           = c[mt][nt][0] + b0;
            buf[row * 132 + col + 1]       = c[mt][nt][1] + b1;
            buf[(row + 8) * 132 + col]     = c[mt][nt][2] + b0;
            buf[(row + 8) * 132 + col + 1] = c[mt][nt][3] + b1;
        }
    }
}

// lorentz_linear epilogue transform in place; optional global store of result rows
__device__ __forceinline__ void lorentz_transform(float* buf, float esc, int tid,
                                                  float* gout, int row0, int maxRow) {
    int wid = tid >> 5, lane = tid & 31;
    for (int i = 0; i < 16; i++) {
        int r = wid * 16 + i;
        float ss = 0.f;
        #pragma unroll
        for (int cc = 0; cc < 4; cc++) {
            int col = lane + cc * 32;
            float v = buf[r * 132 + col];
            if (col > 0) ss += v * v;
        }
        ss = warp_reduce_sum(ss);
        float x0 = buf[r * 132];
        float t  = esc / (1.f + expf(-x0)) + 1.1f;
        float sc = sqrtf((t * t - 1.f) / fmaxf(ss, 1e-8f));
        #pragma unroll
        for (int cc = 0; cc < 4; cc++) {
            int col = lane + cc * 32;
            float v = (col == 0) ? t : buf[r * 132 + col] * sc;
            buf[r * 132 + col] = v;
            if (gout != nullptr && (row0 + r) < maxRow)
                gout[(size_t)(row0 + r) * 128 + col] = v;
        }
    }
}

// ---------------- weight prep: transpose + zero-pad (full fp32, no rounding) ----
__global__ void prep_weights(const float* __restrict__ lqW, const float* __restrict__ lkvW,
                             const float* __restrict__ wqW, const float* __restrict__ wkW,
                             const float* __restrict__ wvW) {
    int m = blockIdx.y;
    const float* W; float* O; int cols, colsPad;
    if (m == 0)      { W = lqW;  O = g_Wt_lq;  cols = QF;  colsPad = QFP; }
    else if (m == 1) { W = lkvW; O = g_Wt_lkv; cols = KVF; colsPad = KVFP; }
    else if (m == 2) { W = wqW;  O = g_Wt_q;   cols = 128; colsPad = 128; }
    else if (m == 3) { W = wkW;  O = g_Wt_k;   cols = 128; colsPad = 128; }
    else             { W = wvW;  O = g_Wt_v;   cols = 128; colsPad = 128; }
    int idx = blockIdx.x * blockDim.x + threadIdx.x;
    if (idx < colsPad * 128) {
        int k = idx >> 7, n = idx & 127;
        O[idx] = (k < cols) ? W[n * cols + k] : 0.f;
    }
}

// ---------------- D kernel: fused node path ----------------
__global__ __launch_bounds__(256, 1) void d_kernel(
    const float* __restrict__ h, const float* __restrict__ te_b,
    const float* __restrict__ lq_b, const float* __restrict__ lq_s,
    const float* __restrict__ wq_b, const float* __restrict__ wq_s,
    const float* __restrict__ wk_b, const float* __restrict__ wk_s,
    const float* __restrict__ wv_b, const float* __restrict__ wv_s,
    const float* __restrict__ att) {
    extern __shared__ float sm[];
    float* s_act  = sm;
    float* s_q    = sm + D_Q;
    float* s_stage= sm + D_Q;          // aliases q (dead until wq epilogue)
    float* s_bmat = sm + D_BMAT;
    float* s_nsc  = sm + D_NSC;
    float* s_nco  = sm + D_NCO;
    float* s_w    = sm + D_W;
    int tid = threadIdx.x, wid = tid >> 5, lane = tid & 31;
    int g = lane >> 2, tig = lane & 3;
    int warpM = wid >> 1, warpN = wid & 1;
    int d0 = blockIdx.x * 128;

    // expmap0 norm pass (200 spatial features)
    for (int i = 0; i < 16; i++) {
        int r = wid * 16 + i, d = d0 + r;
        float ss = 0.f;
        if (d < cD) {
            for (int j = lane; j < 200; j += 32) {
                float v = (j < 100) ? h[(size_t)d * 100 + j] : cosf(te_b[j - 100]);
                ss += v * v;
            }
        }
        ss = warp_reduce_sum(ss);
        if (lane == 0) {
            float n = sqrtf(fmaxf(ss, 1e-8f));
            s_nco[r] = coshf(n);
            s_nsc[r] = sinhf(n) / n;
        }
    }

    float c[2][8][4];
    // GEMM1: features x Wt_lq (K=256 padded)
    zero_c(c);
    for (int kc = 0; kc < 4; kc++) {
        __syncthreads();
        for (int idx = tid; idx < 128 * 64; idx += 256) {
            int r = idx >> 6, kk = idx & 63, k = kc * 64 + kk, d = d0 + r;
            float v = 0.f;
            if (k == 0) v = s_nco[r];
            else if (d < cD && k <= 200) {
                int j = k - 1;
                float raw = (j < 100) ? h[(size_t)d * 100 + j] : cosf(te_b[j - 100]);
                v = s_nsc[r] * raw;
                v = (v >= 0.f) ? v : 0.2f * v;   // leaky (nonlin=True)
            }
            s_stage[r * 68 + kk] = v;
        }
        stage_B(s_bmat, g_Wt_lq + kc * 64 * 128, tid);
        __syncthreads();
        mma_chunk(c, s_stage, 68, s_bmat, warpM, warpN, g, tig);
    }
    __syncthreads();
    epilogue_store(c, s_act, lq_b, warpM, warpN, g, tig);
    __syncthreads();
    lorentz_transform(s_act, expf(*lq_s), tid, nullptr, 0, 0);   // act = Qori
    __syncthreads();

    // GEMM wq: Qori -> Qh (store to global QhD)
    zero_c(c);
    for (int kc = 0; kc < 2; kc++) {
        __syncthreads();
        stage_B(s_bmat, g_Wt_q + kc * 64 * 128, tid);
        __syncthreads();
        mma_chunk(c, s_act + kc * 64, 132, s_bmat, warpM, warpN, g, tig);
    }
    __syncthreads();
    epilogue_store(c, s_q, wq_b, warpM, warpN, g, tig);
    __syncthreads();
    lorentz_transform(s_q, expf(*wq_s), tid, g_QhD, d0, cD);     // q = Qh
    __syncthreads();

    // GEMM wk: Qori -> Kh (overwrite act after all reads)
    zero_c(c);
    for (int kc = 0; kc < 2; kc++) {
        __syncthreads();
        stage_B(s_bmat, g_Wt_k + kc * 64 * 128, tid);
        __syncthreads();
        mma_chunk(c, s_act + kc * 64, 132, s_bmat, warpM, warpN, g, tig);
    }
    __syncthreads();
    epilogue_store(c, s_act, wk_b, warpM, warpN, g, tig);
    __syncthreads();
    lorentz_transform(s_act, expf(*wk_s), tid, nullptr, 0, 0);   // act = Kh
    __syncthreads();

    // self logits -> weights (no max subtraction; logits bounded)
    float attv = *att;
    for (int i = 0; i < 16; i++) {
        int r = wid * 16 + i;
        float inner = 0.f;
        #pragma unroll
        for (int cc = 0; cc < 4; cc++) {
            int col = lane + cc * 32;
            float qv = s_q[r * 132 + col], kv = s_act[r * 132 + col];
            inner += (col == 0) ? -qv * kv : qv * kv;
        }
        inner = warp_reduce_sum(inner);
        if (lane == 0) s_w[r] = expf((2.f + 2.f * inner) / attv);
    }
    __syncthreads();

    // GEMM wv: Kh -> Vh (into q buffer; q fully consumed above)
    zero_c(c);
    for (int kc = 0; kc < 2; kc++) {
        __syncthreads();
        stage_B(s_bmat, g_Wt_v + kc * 64 * 128, tid);
        __syncthreads();
        mma_chunk(c, s_act + kc * 64, 132, s_bmat, warpM, warpN, g, tig);
    }
    __syncthreads();
    epilogue_store(c, s_q, wv_b, warpM, warpN, g, tig);
    __syncthreads();

    // fused transform + acc/ssum init
    float esc3 = expf(*wv_s);
    for (int i = 0; i < 16; i++) {
        int r = wid * 16 + i, d = d0 + r;
        float ss = 0.f;
        #pragma unroll
        for (int cc = 0; cc < 4; cc++) {
            int col = lane + cc * 32;
            float v = s_q[r * 132 + col];
            if (col > 0) ss += v * v;
        }
        ss = warp_reduce_sum(ss);
        float x0 = s_q[r * 132];
        float t  = esc3 / (1.f + expf(-x0)) + 1.1f;
        float sc = sqrtf((t * t - 1.f) / fmaxf(ss, 1e-8f));
        float wgt = s_w[r];
        if (d < cD) {
            #pragma unroll
            for (int cc = 0; cc < 4; cc++) {
                int col = lane + cc * 32;
                float v = (col == 0) ? t : s_q[r * 132 + col] * sc;
                g_acc[(size_t)d * 128 + col] = wgt * v;
            }
            if (lane == 0) g_ssum[d] = wgt;
        }
    }
}

// ---------------- E kernel: fully fused edge path ----------------
__global__ __launch_bounds__(256, 2) void e_kernel(
    const float* __restrict__ h, const float* __restrict__ ef,
    const float* __restrict__ dt, const float* __restrict__ te_w,
    const float* __restrict__ te_b,
    const float* __restrict__ lkv_b, const float* __restrict__ lkv_s,
    const float* __restrict__ wk_b, const float* __restrict__ wk_s,
    const float* __restrict__ wv_b, const float* __restrict__ wv_s,
    const float* __restrict__ att, const int* __restrict__ edge_dst) {
    extern __shared__ float sm[];
    float* s_act  = sm;
    float* s_stage= sm;                 // aliases act (dead until GEMM1 epilogue)
    float* s_bmat = sm + E_BMAT;
    float* s_nsc  = sm + E_NSC;
    float* s_nco  = sm + E_NCO;
    float* s_w    = sm + E_W;
    int*   s_dst  = reinterpret_cast<int*>(sm + E_DST);
    int tid = threadIdx.x, wid = tid >> 5, lane = tid & 31;
    int g = lane >> 2, tig = lane & 3;
    int warpM = wid >> 1, warpN = wid & 1;
    int e0 = blockIdx.x * 128;

    // expmap0 norm pass (300 spatial features)
    for (int i = 0; i < 16; i++) {
        int r = wid * 16 + i, e = e0 + r;
        float ss = 0.f;
        if (e < cE) {
            float dte = dt[e];
            for (int j = lane; j < 300; j += 32) {
                float v;
                if (j < 100)       v = h[(size_t)(cD + e) * 100 + j];
                else if (j < 200)  v = ef[(size_t)e * 100 + (j - 100)];
                else               v = cosf(dte * te_w[j - 200] + te_b[j - 200]);
                ss += v * v;
            }
        }
        ss = warp_reduce_sum(ss);
        if (lane == 0) {
            float n = sqrtf(fmaxf(ss, 1e-8f));
            s_nco[r] = coshf(n);
            s_nsc[r] = sinhf(n) / n;
        }
    }
    if (tid < 128) {
        int e = e0 + tid;
        s_dst[tid] = (e < cE) ? edge_dst[e] : -1;
    }

    float c[2][8][4];
    // GEMM1: features x Wt_lkv (K=320 padded, 5 chunks)
    zero_c(c);
    for (int kc = 0; kc < 5; kc++) {
        __syncthreads();
        for (int idx = tid; idx < 128 * 64; idx += 256) {
            int r = idx >> 6, kk = idx & 63, k = kc * 64 + kk, e = e0 + r;
            float v = 0.f;
            if (k == 0) v = s_nco[r];
            else if (e < cE && k <= 300) {
                int j = k - 1;
                float raw;
                if (j < 100)      raw = h[(size_t)(cD + e) * 100 + j];
                else if (j < 200) raw = ef[(size_t)e * 100 + (j - 100)];
                else              raw = cosf(dt[e] * te_w[j - 200] + te_b[j - 200]);
                v = s_nsc[r] * raw;
                v = (v >= 0.f) ? v : 0.2f * v;
            }
            s_stage[r * 68 + kk] = v;
        }
        stage_B(s_bmat, g_Wt_lkv + kc * 64 * 128, tid);
        __syncthreads();
        mma_chunk(c, s_stage, 68, s_bmat, warpM, warpN, g, tig);
    }
    __syncthreads();
    epilogue_store(c, s_act, lkv_b, warpM, warpN, g, tig);
    __syncthreads();
    lorentz_transform(s_act, expf(*lkv_s), tid, nullptr, 0, 0);   // act = Kori
    __syncthreads();

    // GEMM wk: Kori -> Kh (overwrite act)
    zero_c(c);
    for (int kc = 0; kc < 2; kc++) {
        __syncthreads();
        stage_B(s_bmat, g_Wt_k + kc * 64 * 128, tid);
        __syncthreads();
        mma_chunk(c, s_act + kc * 64, 132, s_bmat, warpM, warpN, g, tig);
    }
    __syncthreads();
    epilogue_store(c, s_act, wk_b, warpM, warpN, g, tig);
    __syncthreads();
    lorentz_transform(s_act, expf(*wk_s), tid, nullptr, 0, 0);    // act = Kh
    __syncthreads();

    // logits + ssum atomics
    float attv = *att;
    for (int i = 0; i < 16; i++) {
        int r = wid * 16 + i;
        int dv = s_dst[r];
        float inner = 0.f;
        if (dv >= 0) {
            #pragma unroll
            for (int cc = 0; cc < 4; cc++) {
                int col = lane + cc * 32;
                float kv = s_act[r * 132 + col];
                float qv = g_QhD[(size_t)dv * 128 + col];
                inner += (col == 0) ? -kv * qv : kv * qv;
            }
        }
        inner = warp_reduce_sum(inner);
        if (lane == 0) {
            float wgt = (dv >= 0) ? expf((2.f + 2.f * inner) / attv) : 0.f;
            s_w[r] = wgt;
            if (dv >= 0) atomicAdd(&g_ssum[dv], wgt);
        }
    }
    __syncthreads();

    // GEMM wv: Kh -> Vh (overwrite act)
    zero_c(c);
    for (int kc = 0; kc < 2; kc++) {
        __syncthreads();
        stage_B(s_bmat, g_Wt_v + kc * 64 * 128, tid);
        __syncthreads();
        mma_chunk(c, s_act + kc * 64, 132, s_bmat, warpM, warpN, g, tig);
    }
    __syncthreads();
    epilogue_store(c, s_act, wv_b, warpM, warpN, g, tig);
    __syncthreads();

    // fused transform + weighted scatter
    float esc3 = expf(*wv_s);
    for (int i = 0; i < 16; i++) {
        int r = wid * 16 + i;
        int dv = s_dst[r];
        float ss = 0.f;
        #pragma unroll
        for (int cc = 0; cc < 4; cc++) {
            int col = lane + cc * 32;
            float v = s_act[r * 132 + col];
            if (col > 0) ss += v * v;
        }
        ss = warp_reduce_sum(ss);
        float x0 = s_act[r * 132];
        float t  = esc3 / (1.f + expf(-x0)) + 1.1f;
        float sc = sqrtf((t * t - 1.f) / fmaxf(ss, 1e-8f));
        float wgt = s_w[r];
        if (dv >= 0) {
            #pragma unroll
            for (int cc = 0; cc < 4; cc++) {
                int col = lane + cc * 32;
                float v = (col == 0) ? t : s_act[r * 132 + col] * sc;
                atomicAdd(&g_acc[(size_t)dv * 128 + col], wgt * v);
            }
        }
    }
}

// ---------------- finalize ----------------
__global__ void finalize_kernel(float* __restrict__ out) {
    int d = blockIdx.x * 4 + (threadIdx.x >> 5);
    int lane = threadIdx.x & 31;
    if (d >= cD) return;
    float inv_s = 1.f / g_ssum[d];
    float rv[4];
    float sq = 0.f;
    #pragma unroll
    for (int i = 0; i < 4; i++) {
        int c = lane + 32 * i;
        float v = g_acc[(size_t)d * 128 + c] * inv_s;
        rv[i] = v;
        if (c != 0) sq += v * v;
    }
    sq = warp_reduce_sum(sq);
    float r0 = __shfl_sync(0xffffffffu, rv[0], 0);
    float neg_inner = r0 * r0 - sq;
    float denom = sqrtf(fmaxf(fabsf(neg_inner), 1e-8f));
    float a = fmaxf(r0 / denom, 1.f + 1e-7f);
    float coef = acoshf(a) / sqrtf(fmaxf(a * a - 1.f, 1e-8f));
    #pragma unroll
    for (int i = 0; i < 4; i++) {
        int c = lane + 32 * i;
        out[(size_t)d * 128 + c] = (c == 0) ? 0.f : coef * (rv[i] / denom);
    }
}

// ---------------- launch ----------------
extern "C" void kernel_launch(void* const* d_in, const int* in_sizes, int n_in,
                              void* d_out, int out_size) {
    const float* h     = (const float*)d_in[0];
    const float* ef    = (const float*)d_in[1];
    const float* dt    = (const float*)d_in[2];
    const float* te_w  = (const float*)d_in[3];
    const float* te_b  = (const float*)d_in[4];
    const float* lq_W  = (const float*)d_in[5];
    const float* lq_b  = (const float*)d_in[6];
    const float* lq_s  = (const float*)d_in[7];
    const float* lkv_W = (const float*)d_in[8];
    const float* lkv_b = (const float*)d_in[9];
    const float* lkv_s = (const float*)d_in[10];
    const float* wq_W  = (const float*)d_in[11];
    const float* wq_b  = (const float*)d_in[12];
    const float* wq_s  = (const float*)d_in[13];
    const float* wk_W  = (const float*)d_in[14];
    const float* wk_b  = (const float*)d_in[15];
    const float* wk_s  = (const float*)d_in[16];
    const float* wv_W  = (const float*)d_in[17];
    const float* wv_b  = (const float*)d_in[18];
    const float* wv_s  = (const float*)d_in[19];
    const float* att   = (const float*)d_in[20];
    const int*   edst  = (const int*)d_in[21];
    float* out = (float*)d_out;

    cudaFuncSetAttribute(d_kernel, cudaFuncAttributeMaxDynamicSharedMemorySize,
                         D_TOTAL_F * 4);
    cudaFuncSetAttribute(e_kernel, cudaFuncAttributeMaxDynamicSharedMemorySize,
                         E_TOTAL_F * 4);

    prep_weights<<<dim3((KVFP * 128 + 255) / 256, 5), 256>>>(lq_W, lkv_W, wq_W, wk_W, wv_W);
    d_kernel<<<(cD + 127) / 128, 256, D_TOTAL_F * 4>>>(
        h, te_b, lq_b, lq_s, wq_b, wq_s, wk_b, wk_s, wv_b, wv_s, att);
    e_kernel<<<(cE + 127) / 128, 256, E_TOTAL_F * 4>>>(
        h, ef, dt, te_w, te_b, lkv_b, lkv_s, wk_b, wk_s, wv_b, wv_s, att, edst);
    finalize_kernel<<<(cD + 3) / 4, 128>>>(out);
}

// round 7
// speedup vs baseline: 1.2582x; 1.2014x over previous
#include <cuda_runtime.h>
#include <math.h>
#include <stdint.h>

// ---------------- problem constants ----------------
constexpr int cD   = 15000;
constexpr int cE   = 300000;
constexpr int QF   = 201;   // DT+DN+1
constexpr int QFP  = 256;   // padded to 4 chunks of 64
constexpr int KVF  = 301;   // DT+DN+DE+1
constexpr int KVFP = 320;   // padded to 5 chunks of 64

// ---------------- scratch (device globals) ----------------
__device__ float g_QhD [(size_t)cD * 128];
__device__ float g_acc [(size_t)cD * 128];
__device__ float g_ssum[cD];
__device__ float g_Wt_lq [QFP  * 128];
__device__ float g_Wt_lkv[KVFP * 128];
__device__ float g_Wt_q  [128 * 128];
__device__ float g_Wt_k  [128 * 128];
__device__ float g_Wt_v  [128 * 128];

// ---------------- helpers ----------------
__device__ __forceinline__ float warp_reduce_sum(float v) {
    #pragma unroll
    for (int o = 16; o > 0; o >>= 1) v += __shfl_xor_sync(0xffffffffu, v, o);
    return v;
}
__device__ __forceinline__ float to_tf32(float x) {
    uint32_t u;
    asm("cvt.rna.tf32.f32 %0, %1;" : "=r"(u) : "f"(x));
    return __uint_as_float(u);
}
__device__ __forceinline__ void split_tf32(float x, float& hi, float& lo) {
    hi = to_tf32(x);
    lo = to_tf32(x - hi);
}
// precise-enough cos for |x| <= ~2e4: 2-term Cody-Waite + __cosf (err ~1e-6 abs)
__device__ __forceinline__ float fast_cos(float x) {
    float kf = rintf(x * 0.15915494309189535f);
    float r  = fmaf(-kf, 6.2831854820251465f, x);    // 2pi hi (fp32)
    r        = fmaf(-kf, -1.7484556e-7f, r);         // 2pi lo
    return __cosf(r);
}
__device__ __forceinline__ void mma_tf32(float* c, float a0, float a1, float a2, float a3,
                                         float b0, float b1) {
    asm volatile(
        "mma.sync.aligned.m16n8k8.row.col.f32.tf32.tf32.f32 "
        "{%0,%1,%2,%3}, {%4,%5,%6,%7}, {%8,%9}, {%0,%1,%2,%3};"
        : "+f"(c[0]), "+f"(c[1]), "+f"(c[2]), "+f"(c[3])
        : "r"(__float_as_uint(a0)), "r"(__float_as_uint(a1)),
          "r"(__float_as_uint(a2)), "r"(__float_as_uint(a3)),
          "r"(__float_as_uint(b0)), "r"(__float_as_uint(b1)));
}

// ---------------- smem layouts ----------------
constexpr int ACT_F   = 128 * 132;          // stride 132 (==4 mod 32)
constexpr int BMAT_F  = 64 * 136;           // stride 136 (==8 mod 32)

// E kernel: [act | bmat | nsc | nco | w | dst | ss | dtv]; stage aliases act
constexpr int E_BMAT = ACT_F;
constexpr int E_NSC  = E_BMAT + BMAT_F;
constexpr int E_NCO  = E_NSC + 128;
constexpr int E_W    = E_NCO + 128;
constexpr int E_DST  = E_W + 128;
constexpr int E_SS   = E_DST + 128;
constexpr int E_DTV  = E_SS + 128;
constexpr int E_TOTAL_F = E_DTV + 128;      // ~103.5 KB

// D kernel: [act | q | bmat | nsc | nco | w | ss | ztf]; stage aliases q
constexpr int D_Q    = ACT_F;
constexpr int D_BMAT = D_Q + ACT_F;
constexpr int D_NSC  = D_BMAT + BMAT_F;
constexpr int D_NCO  = D_NSC + 128;
constexpr int D_W    = D_NCO + 128;
constexpr int D_SS   = D_W + 128;
constexpr int D_ZTF  = D_SS + 128;
constexpr int D_TOTAL_F = D_ZTF + 128;      // ~169 KB

// one K-chunk (64) of 3xTF32 mma accumulation. warp tile = 32 rows x 64 cols.
__device__ __forceinline__ void mma_chunk(float (&c)[2][8][4], const float* sA, int ldA,
                                          const float* sB,
                                          int warpM, int warpN, int g, int tig) {
    #pragma unroll
    for (int kt = 0; kt < 8; kt++) {
        const int k0 = kt * 8;
        float ah[2][4], al[2][4];
        #pragma unroll
        for (int mt = 0; mt < 2; mt++) {
            const float* pr = sA + (warpM * 32 + mt * 16 + g) * ldA + k0 + tig;
            split_tf32(pr[0],            ah[mt][0], al[mt][0]);
            split_tf32(pr[8 * ldA],      ah[mt][1], al[mt][1]);
            split_tf32(pr[4],            ah[mt][2], al[mt][2]);
            split_tf32(pr[8 * ldA + 4],  ah[mt][3], al[mt][3]);
        }
        #pragma unroll
        for (int nt = 0; nt < 8; nt++) {
            int col = warpN * 64 + nt * 8 + g;
            float b0h, b0l, b1h, b1l;
            split_tf32(sB[(k0 + tig) * 136 + col],     b0h, b0l);
            split_tf32(sB[(k0 + tig + 4) * 136 + col], b1h, b1l);
            #pragma unroll
            for (int mt = 0; mt < 2; mt++) {
                mma_tf32(c[mt][nt], al[mt][0], al[mt][1], al[mt][2], al[mt][3], b0h, b1h);
                mma_tf32(c[mt][nt], ah[mt][0], ah[mt][1], ah[mt][2], ah[mt][3], b0l, b1l);
                mma_tf32(c[mt][nt], ah[mt][0], ah[mt][1], ah[mt][2], ah[mt][3], b0h, b1h);
            }
        }
    }
}

__device__ __forceinline__ void zero_c(float (&c)[2][8][4]) {
    #pragma unroll
    for (int mt = 0; mt < 2; mt++)
        #pragma unroll
        for (int nt = 0; nt < 8; nt++)
            #pragma unroll
            for (int i = 0; i < 4; i++) c[mt][nt][i] = 0.f;
}

__device__ __forceinline__ void stage_B(float* sB, const float* Wsrc, int tid) {
    #pragma unroll
    for (int idx = tid; idx < 64 * 32; idx += 256) {
        int k = idx >> 5, n4 = (idx & 31) << 2;
        float4 v = *reinterpret_cast<const float4*>(Wsrc + k * 128 + n4);
        *reinterpret_cast<float4*>(sB + k * 136 + n4) = v;
    }
}

// plain epilogue: c + bias -> buf
__device__ __forceinline__ void epilogue_store(const float (&c)[2][8][4], float* buf,
                                               const float* __restrict__ bias,
                                               int warpM, int warpN, int g, int tig) {
    #pragma unroll
    for (int mt = 0; mt < 2; mt++) {
        int row = warpM * 32 + mt * 16 + g;
        #pragma unroll
        for (int nt = 0; nt < 8; nt++) {
            int col = warpN * 64 + nt * 8 + tig * 2;
            float b0 = bias[col], b1 = bias[col + 1];
            buf[row * 132 + col]           = c[mt][nt][0] + b0;
            buf[row * 132 + col + 1]       = c[mt][nt][1] + b1;
            buf[(row + 8) * 132 + col]     = c[mt][nt][2] + b0;
            buf[(row + 8) * 132 + col + 1] = c[mt][nt][3] + b1;
        }
    }
}

// GEMM1 epilogue with deferred expmap0 scale:
// x = sc_row * c + co_row * W0[col] + bias[col]
__device__ __forceinline__ void epilogue_g1(const float (&c)[2][8][4], float* buf,
                                            const float* __restrict__ bias,
                                            const float* __restrict__ W0,
                                            const float* s_nsc, const float* s_nco,
                                            int warpM, int warpN, int g, int tig) {
    #pragma unroll
    for (int mt = 0; mt < 2; mt++) {
        int row = warpM * 32 + mt * 16 + g;
        float sc0 = s_nsc[row],     co0 = s_nco[row];
        float sc1 = s_nsc[row + 8], co1 = s_nco[row + 8];
        #pragma unroll
        for (int nt = 0; nt < 8; nt++) {
            int col = warpN * 64 + nt * 8 + tig * 2;
            float b0 = bias[col], b1 = bias[col + 1];
            float w0 = W0[col],   w1 = W0[col + 1];
            buf[row * 132 + col]           = fmaf(sc0, c[mt][nt][0], fmaf(co0, w0, b0));
            buf[row * 132 + col + 1]       = fmaf(sc0, c[mt][nt][1], fmaf(co0, w1, b1));
            buf[(row + 8) * 132 + col]     = fmaf(sc1, c[mt][nt][2], fmaf(co1, w0, b0));
            buf[(row + 8) * 132 + col + 1] = fmaf(sc1, c[mt][nt][3], fmaf(co1, w1, b1));
        }
    }
}

// lorentz_linear epilogue transform in place; optional global store of result rows
__device__ __forceinline__ void lorentz_transform(float* buf, float esc, int tid,
                                                  float* gout, int row0, int maxRow) {
    int wid = tid >> 5, lane = tid & 31;
    for (int i = 0; i < 16; i++) {
        int r = wid * 16 + i;
        float ss = 0.f;
        #pragma unroll
        for (int cc = 0; cc < 4; cc++) {
            int col = lane + cc * 32;
            float v = buf[r * 132 + col];
            if (col > 0) ss += v * v;
        }
        ss = warp_reduce_sum(ss);
        float x0 = buf[r * 132];
        float t  = esc / (1.f + expf(-x0)) + 1.1f;
        float sc = sqrtf((t * t - 1.f) / fmaxf(ss, 1e-8f));
        #pragma unroll
        for (int cc = 0; cc < 4; cc++) {
            int col = lane + cc * 32;
            float v = (col == 0) ? t : buf[r * 132 + col] * sc;
            buf[r * 132 + col] = v;
            if (gout != nullptr && (row0 + r) < maxRow)
                gout[(size_t)(row0 + r) * 128 + col] = v;
        }
    }
}

// ---------------- weight prep: transpose + zero-pad (full fp32) ----------------
__global__ void prep_weights(const float* __restrict__ lqW, const float* __restrict__ lkvW,
                             const float* __restrict__ wqW, const float* __restrict__ wkW,
                             const float* __restrict__ wvW) {
    int m = blockIdx.y;
    const float* W; float* O; int cols, colsPad;
    if (m == 0)      { W = lqW;  O = g_Wt_lq;  cols = QF;  colsPad = QFP; }
    else if (m == 1) { W = lkvW; O = g_Wt_lkv; cols = KVF; colsPad = KVFP; }
    else if (m == 2) { W = wqW;  O = g_Wt_q;   cols = 128; colsPad = 128; }
    else if (m == 3) { W = wkW;  O = g_Wt_k;   cols = 128; colsPad = 128; }
    else             { W = wvW;  O = g_Wt_v;   cols = 128; colsPad = 128; }
    int idx = blockIdx.x * blockDim.x + threadIdx.x;
    if (idx < colsPad * 128) {
        int k = idx >> 7, n = idx & 127;
        O[idx] = (k < cols) ? W[n * cols + k] : 0.f;
    }
}

// ---------------- D kernel: fused node path ----------------
__global__ __launch_bounds__(256, 1) void d_kernel(
    const float* __restrict__ h, const float* __restrict__ te_b,
    const float* __restrict__ lq_b, const float* __restrict__ lq_s,
    const float* __restrict__ wq_b, const float* __restrict__ wq_s,
    const float* __restrict__ wk_b, const float* __restrict__ wk_s,
    const float* __restrict__ wv_b, const float* __restrict__ wv_s,
    const float* __restrict__ att) {
    extern __shared__ float sm[];
    float* s_act  = sm;
    float* s_stage= sm + D_Q;          // aliases q (dead until wq epilogue)
    float* s_q    = sm + D_Q;
    float* s_bmat = sm + D_BMAT;
    float* s_nsc  = sm + D_NSC;
    float* s_nco  = sm + D_NCO;
    float* s_w    = sm + D_W;
    float* s_ss   = sm + D_SS;
    float* s_ztf  = sm + D_ZTF;
    int tid = threadIdx.x, wid = tid >> 5, lane = tid & 31;
    int g = lane >> 2, tig = lane & 3;
    int warpM = wid >> 1, warpN = wid & 1;
    int d0 = blockIdx.x * 128;

    if (tid < 128) {
        s_ss[tid]  = 0.f;
        s_ztf[tid] = (tid < 100) ? cosf(te_b[tid]) : 0.f;
    }

    float c[2][8][4];
    // GEMM1: raw features x Wt_lq (K=256 padded); expmap0 scale deferred
    zero_c(c);
    for (int kc = 0; kc < 4; kc++) {
        __syncthreads();
        for (int idx = tid; idx < 128 * 64; idx += 256) {
            int r = idx >> 6, kk = idx & 63, k = kc * 64 + kk, d = d0 + r;
            float raw = 0.f;
            if (d < cD && k >= 1 && k <= 200) {
                int j = k - 1;
                raw = (j < 100) ? h[(size_t)d * 100 + j] : s_ztf[j - 100];
            }
            s_stage[r * 68 + kk] = (raw >= 0.f) ? raw : 0.2f * raw;  // leaky(raw); sc>0
            float sq = warp_reduce_sum(raw * raw);
            if (lane == 0) atomicAdd(&s_ss[r], sq);
        }
        stage_B(s_bmat, g_Wt_lq + kc * 64 * 128, tid);
        __syncthreads();
        mma_chunk(c, s_stage, 68, s_bmat, warpM, warpN, g, tig);
    }
    __syncthreads();
    if (tid < 128) {
        float n = sqrtf(fmaxf(s_ss[tid], 1e-8f));
        s_nco[tid] = coshf(n);
        s_nsc[tid] = sinhf(n) / n;
    }
    __syncthreads();
    epilogue_g1(c, s_act, lq_b, g_Wt_lq, s_nsc, s_nco, warpM, warpN, g, tig);
    __syncthreads();
    lorentz_transform(s_act, expf(*lq_s), tid, nullptr, 0, 0);   // act = Qori
    __syncthreads();

    // GEMM wq: Qori -> Qh (store to global QhD)
    zero_c(c);
    for (int kc = 0; kc < 2; kc++) {
        __syncthreads();
        stage_B(s_bmat, g_Wt_q + kc * 64 * 128, tid);
        __syncthreads();
        mma_chunk(c, s_act + kc * 64, 132, s_bmat, warpM, warpN, g, tig);
    }
    __syncthreads();
    epilogue_store(c, s_q, wq_b, warpM, warpN, g, tig);
    __syncthreads();
    lorentz_transform(s_q, expf(*wq_s), tid, g_QhD, d0, cD);     // q = Qh
    __syncthreads();

    // GEMM wk: Qori -> Kh (overwrite act after all reads)
    zero_c(c);
    for (int kc = 0; kc < 2; kc++) {
        __syncthreads();
        stage_B(s_bmat, g_Wt_k + kc * 64 * 128, tid);
        __syncthreads();
        mma_chunk(c, s_act + kc * 64, 132, s_bmat, warpM, warpN, g, tig);
    }
    __syncthreads();
    epilogue_store(c, s_act, wk_b, warpM, warpN, g, tig);
    __syncthreads();
    lorentz_transform(s_act, expf(*wk_s), tid, nullptr, 0, 0);   // act = Kh
    __syncthreads();

    // self logits -> weights (no max subtraction; logits bounded)
    float attv = *att;
    for (int i = 0; i < 16; i++) {
        int r = wid * 16 + i;
        float inner = 0.f;
        #pragma unroll
        for (int cc = 0; cc < 4; cc++) {
            int col = lane + cc * 32;
            float qv = s_q[r * 132 + col], kv = s_act[r * 132 + col];
            inner += (col == 0) ? -qv * kv : qv * kv;
        }
        inner = warp_reduce_sum(inner);
        if (lane == 0) s_w[r] = expf((2.f + 2.f * inner) / attv);
    }
    __syncthreads();

    // GEMM wv: Kh -> Vh (into q buffer; q fully consumed above)
    zero_c(c);
    for (int kc = 0; kc < 2; kc++) {
        __syncthreads();
        stage_B(s_bmat, g_Wt_v + kc * 64 * 128, tid);
        __syncthreads();
        mma_chunk(c, s_act + kc * 64, 132, s_bmat, warpM, warpN, g, tig);
    }
    __syncthreads();
    epilogue_store(c, s_q, wv_b, warpM, warpN, g, tig);
    __syncthreads();

    // fused transform + acc/ssum init
    float esc3 = expf(*wv_s);
    for (int i = 0; i < 16; i++) {
        int r = wid * 16 + i, d = d0 + r;
        float ss = 0.f;
        #pragma unroll
        for (int cc = 0; cc < 4; cc++) {
            int col = lane + cc * 32;
            float v = s_q[r * 132 + col];
            if (col > 0) ss += v * v;
        }
        ss = warp_reduce_sum(ss);
        float x0 = s_q[r * 132];
        float t  = esc3 / (1.f + expf(-x0)) + 1.1f;
        float sc = sqrtf((t * t - 1.f) / fmaxf(ss, 1e-8f));
        float wgt = s_w[r];
        if (d < cD) {
            #pragma unroll
            for (int cc = 0; cc < 4; cc++) {
                int col = lane + cc * 32;
                float v = (col == 0) ? t : s_q[r * 132 + col] * sc;
                g_acc[(size_t)d * 128 + col] = wgt * v;
            }
            if (lane == 0) g_ssum[d] = wgt;
        }
    }
}

// ---------------- E kernel: fully fused edge path ----------------
__global__ __launch_bounds__(256, 2) void e_kernel(
    const float* __restrict__ h, const float* __restrict__ ef,
    const float* __restrict__ dt, const float* __restrict__ te_w,
    const float* __restrict__ te_b,
    const float* __restrict__ lkv_b, const float* __restrict__ lkv_s,
    const float* __restrict__ wk_b, const float* __restrict__ wk_s,
    const float* __restrict__ wv_b, const float* __restrict__ wv_s,
    const float* __restrict__ att, const int* __restrict__ edge_dst) {
    extern __shared__ float sm[];
    float* s_act  = sm;
    float* s_stage= sm;                 // aliases act (dead until GEMM1 epilogue)
    float* s_bmat = sm + E_BMAT;
    float* s_nsc  = sm + E_NSC;
    float* s_nco  = sm + E_NCO;
    float* s_w    = sm + E_W;
    int*   s_dst  = reinterpret_cast<int*>(sm + E_DST);
    float* s_ss   = sm + E_SS;
    float* s_dtv  = sm + E_DTV;
    int tid = threadIdx.x, wid = tid >> 5, lane = tid & 31;
    int g = lane >> 2, tig = lane & 3;
    int warpM = wid >> 1, warpN = wid & 1;
    int e0 = blockIdx.x * 128;

    if (tid < 128) {
        int e = e0 + tid;
        bool v = (e < cE);
        s_dst[tid] = v ? edge_dst[e] : -1;
        s_dtv[tid] = v ? dt[e] : 0.f;
        s_ss[tid]  = 0.f;
    }

    float c[2][8][4];
    // GEMM1: raw features x Wt_lkv (K=320 padded); expmap0 scale deferred
    zero_c(c);
    for (int kc = 0; kc < 5; kc++) {
        __syncthreads();
        for (int idx = tid; idx < 128 * 64; idx += 256) {
            int r = idx >> 6, kk = idx & 63, k = kc * 64 + kk, e = e0 + r;
            float raw = 0.f;
            if (e < cE && k >= 1 && k <= 300) {
                int j = k - 1;
                if (j < 100)      raw = h[(size_t)(cD + e) * 100 + j];
                else if (j < 200) raw = ef[(size_t)e * 100 + (j - 100)];
                else              raw = fast_cos(fmaf(s_dtv[r], te_w[j - 200], te_b[j - 200]));
            }
            s_stage[r * 68 + kk] = (raw >= 0.f) ? raw : 0.2f * raw;  // leaky(raw)
            float sq = warp_reduce_sum(raw * raw);
            if (lane == 0) atomicAdd(&s_ss[r], sq);
        }
        stage_B(s_bmat, g_Wt_lkv + kc * 64 * 128, tid);
        __syncthreads();
        mma_chunk(c, s_stage, 68, s_bmat, warpM, warpN, g, tig);
    }
    __syncthreads();
    if (tid < 128) {
        float n = sqrtf(fmaxf(s_ss[tid], 1e-8f));
        s_nco[tid] = coshf(n);
        s_nsc[tid] = sinhf(n) / n;
    }
    __syncthreads();
    epilogue_g1(c, s_act, lkv_b, g_Wt_lkv, s_nsc, s_nco, warpM, warpN, g, tig);
    __syncthreads();
    lorentz_transform(s_act, expf(*lkv_s), tid, nullptr, 0, 0);   // act = Kori
    __syncthreads();

    // GEMM wk: Kori -> Kh (overwrite act)
    zero_c(c);
    for (int kc = 0; kc < 2; kc++) {
        __syncthreads();
        stage_B(s_bmat, g_Wt_k + kc * 64 * 128, tid);
        __syncthreads();
        mma_chunk(c, s_act + kc * 64, 132, s_bmat, warpM, warpN, g, tig);
    }
    __syncthreads();
    epilogue_store(c, s_act, wk_b, warpM, warpN, g, tig);
    __syncthreads();
    lorentz_transform(s_act, expf(*wk_s), tid, nullptr, 0, 0);    // act = Kh
    __syncthreads();

    // logits + ssum atomics
    float attv = *att;
    for (int i = 0; i < 16; i++) {
        int r = wid * 16 + i;
        int dv = s_dst[r];
        float inner = 0.f;
        if (dv >= 0) {
            #pragma unroll
            for (int cc = 0; cc < 4; cc++) {
                int col = lane + cc * 32;
                float kv = s_act[r * 132 + col];
                float qv = g_QhD[(size_t)dv * 128 + col];
                inner += (col == 0) ? -kv * qv : kv * qv;
            }
        }
        inner = warp_reduce_sum(inner);
        if (lane == 0) {
            float wgt = (dv >= 0) ? expf((2.f + 2.f * inner) / attv) : 0.f;
            s_w[r] = wgt;
            if (dv >= 0) atomicAdd(&g_ssum[dv], wgt);
        }
    }
    __syncthreads();

    // GEMM wv: Kh -> Vh (overwrite act)
    zero_c(c);
    for (int kc = 0; kc < 2; kc++) {
        __syncthreads();
        stage_B(s_bmat, g_Wt_v + kc * 64 * 128, tid);
        __syncthreads();
        mma_chunk(c, s_act + kc * 64, 132, s_bmat, warpM, warpN, g, tig);
    }
    __syncthreads();
    epilogue_store(c, s_act, wv_b, warpM, warpN, g, tig);
    __syncthreads();

    // fused transform + weighted scatter
    float esc3 = expf(*wv_s);
    for (int i = 0; i < 16; i++) {
        int r = wid * 16 + i;
        int dv = s_dst[r];
        float ss = 0.f;
        #pragma unroll
        for (int cc = 0; cc < 4; cc++) {
            int col = lane + cc * 32;
            float v = s_act[r * 132 + col];
            if (col > 0) ss += v * v;
        }
        ss = warp_reduce_sum(ss);
        float x0 = s_act[r * 132];
        float t  = esc3 / (1.f + expf(-x0)) + 1.1f;
        float sc = sqrtf((t * t - 1.f) / fmaxf(ss, 1e-8f));
        float wgt = s_w[r];
        if (dv >= 0) {
            #pragma unroll
            for (int cc = 0; cc < 4; cc++) {
                int col = lane + cc * 32;
                float v = (col == 0) ? t : s_act[r * 132 + col] * sc;
                atomicAdd(&g_acc[(size_t)dv * 128 + col], wgt * v);
            }
        }
    }
}

// ---------------- finalize ----------------
__global__ void finalize_kernel(float* __restrict__ out) {
    int d = blockIdx.x * 4 + (threadIdx.x >> 5);
    int lane = threadIdx.x & 31;
    if (d >= cD) return;
    float inv_s = 1.f / g_ssum[d];
    float rv[4];
    float sq = 0.f;
    #pragma unroll
    for (int i = 0; i < 4; i++) {
        int c = lane + 32 * i;
        float v = g_acc[(size_t)d * 128 + c] * inv_s;
        rv[i] = v;
        if (c != 0) sq += v * v;
    }
    sq = warp_reduce_sum(sq);
    float r0 = __shfl_sync(0xffffffffu, rv[0], 0);
    float neg_inner = r0 * r0 - sq;
    float denom = sqrtf(fmaxf(fabsf(neg_inner), 1e-8f));
    float a = fmaxf(r0 / denom, 1.f + 1e-7f);
    float coef = acoshf(a) / sqrtf(fmaxf(a * a - 1.f, 1e-8f));
    #pragma unroll
    for (int i = 0; i < 4; i++) {
        int c = lane + 32 * i;
        out[(size_t)d * 128 + c] = (c == 0) ? 0.f : coef * (rv[i] / denom);
    }
}

// ---------------- launch ----------------
extern "C" void kernel_launch(void* const* d_in, const int* in_sizes, int n_in,
                              void* d_out, int out_size) {
    const float* h     = (const float*)d_in[0];
    const float* ef    = (const float*)d_in[1];
    const float* dt    = (const float*)d_in[2];
    const float* te_w  = (const float*)d_in[3];
    const float* te_b  = (const float*)d_in[4];
    const float* lq_W  = (const float*)d_in[5];
    const float* lq_b  = (const float*)d_in[6];
    const float* lq_s  = (const float*)d_in[7];
    const float* lkv_W = (const float*)d_in[8];
    const float* lkv_b = (const float*)d_in[9];
    const float* lkv_s = (const float*)d_in[10];
    const float* wq_W  = (const float*)d_in[11];
    const float* wq_b  = (const float*)d_in[12];
    const float* wq_s  = (const float*)d_in[13];
    const float* wk_W  = (const float*)d_in[14];
    const float* wk_b  = (const float*)d_in[15];
    const float* wk_s  = (const float*)d_in[16];
    const float* wv_W  = (const float*)d_in[17];
    const float* wv_b  = (const float*)d_in[18];
    const float* wv_s  = (const float*)d_in[19];
    const float* att   = (const float*)d_in[20];
    const int*   edst  = (const int*)d_in[21];
    float* out = (float*)d_out;

    cudaFuncSetAttribute(d_kernel, cudaFuncAttributeMaxDynamicSharedMemorySize,
                         D_TOTAL_F * 4);
    cudaFuncSetAttribute(e_kernel, cudaFuncAttributeMaxDynamicSharedMemorySize,
                         E_TOTAL_F * 4);

    prep_weights<<<dim3((KVFP * 128 + 255) / 256, 5), 256>>>(lq_W, lkv_W, wq_W, wk_W, wv_W);
    d_kernel<<<(cD + 127) / 128, 256, D_TOTAL_F * 4>>>(
        h, te_b, lq_b, lq_s, wq_b, wq_s, wk_b, wk_s, wv_b, wv_s, att);
    e_kernel<<<(cE + 127) / 128, 256, E_TOTAL_F * 4>>>(
        h, ef, dt, te_w, te_b, lkv_b, lkv_s, wk_b, wk_s, wv_b, wv_s, att, edst);
    finalize_kernel<<<(cD + 3) / 4, 128>>>(out);
}

// round 9
// speedup vs baseline: 1.8659x; 1.4830x over previous
#include <cuda_runtime.h>
#include <math.h>
#include <stdint.h>

// ---------------- problem constants ----------------
constexpr int cD   = 15000;
constexpr int cE   = 300000;
constexpr int QF   = 201;   // DT+DN+1
constexpr int QFP  = 256;   // shifted K=200, padded to 4 chunks of 64
constexpr int KVF  = 301;   // DT+DN+DE+1
constexpr int KVFP = 320;   // shifted K=300, padded to 5 chunks of 64

// ---------------- scratch (device globals) ----------------
__device__ float g_QhD [(size_t)cD * 128];
__device__ float g_acc [(size_t)cD * 128];
__device__ float g_ssum[cD];
__device__ float g_Wt_lq [QFP  * 128];   // shifted: row k = W[:, k+1]
__device__ float g_Wt_lkv[KVFP * 128];   // shifted
__device__ float g_Wt_q  [128 * 128];    // unshifted (row 0 = W[:,0] = 0)
__device__ float g_Wt_k  [128 * 128];
__device__ float g_Wt_v  [128 * 128];

// ---------------- helpers ----------------
__device__ __forceinline__ float warp_reduce_sum(float v) {
    #pragma unroll
    for (int o = 16; o > 0; o >>= 1) v += __shfl_xor_sync(0xffffffffu, v, o);
    return v;
}
__device__ __forceinline__ float to_tf32(float x) {
    uint32_t u;
    asm("cvt.rna.tf32.f32 %0, %1;" : "=r"(u) : "f"(x));
    return __uint_as_float(u);
}
__device__ __forceinline__ void split_tf32(float x, float& hi, float& lo) {
    hi = to_tf32(x);
    lo = to_tf32(x - hi);
}
// precise-enough cos for |x| <= ~2e4: 2-term Cody-Waite + __cosf (err ~1e-6 abs)
__device__ __forceinline__ float fast_cos(float x) {
    float kf = rintf(x * 0.15915494309189535f);
    float r  = fmaf(-kf, 6.2831854820251465f, x);
    r        = fmaf(-kf, -1.7484556e-7f, r);
    return __cosf(r);
}
__device__ __forceinline__ float leaky(float v) { return (v >= 0.f) ? v : 0.2f * v; }
__device__ __forceinline__ void mma_tf32(float* c, float a0, float a1, float a2, float a3,
                                         float b0, float b1) {
    asm volatile(
        "mma.sync.aligned.m16n8k8.row.col.f32.tf32.tf32.f32 "
        "{%0,%1,%2,%3}, {%4,%5,%6,%7}, {%8,%9}, {%0,%1,%2,%3};"
        : "+f"(c[0]), "+f"(c[1]), "+f"(c[2]), "+f"(c[3])
        : "r"(__float_as_uint(a0)), "r"(__float_as_uint(a1)),
          "r"(__float_as_uint(a2)), "r"(__float_as_uint(a3)),
          "r"(__float_as_uint(b0)), "r"(__float_as_uint(b1)));
}

// ---------------- smem layouts ----------------
constexpr int ACT_F   = 128 * 132;          // stride 132
constexpr int BMAT_F  = 64 * 136;           // stride 136

// E: [act | bmat | ss | s | t | w | dst | dtv]; stage aliases act
constexpr int E_BMAT = ACT_F;
constexpr int E_SS   = E_BMAT + BMAT_F;
constexpr int E_S    = E_SS + 128;
constexpr int E_T    = E_S + 128;
constexpr int E_W    = E_T + 128;
constexpr int E_DST  = E_W + 128;
constexpr int E_DTV  = E_DST + 128;
constexpr int E_TOTAL_F = E_DTV + 128;      // ~103.5 KB

// D: [act | q | bmat | ss | s | t | sq | tq | w | ztf]; stage aliases q
constexpr int D_Q    = ACT_F;
constexpr int D_BMAT = D_Q + ACT_F;
constexpr int D_SS   = D_BMAT + BMAT_F;
constexpr int D_S    = D_SS + 128;
constexpr int D_T    = D_S + 128;
constexpr int D_SQ   = D_T + 128;
constexpr int D_TQ   = D_SQ + 128;
constexpr int D_W    = D_TQ + 128;
constexpr int D_ZTF  = D_W + 128;
constexpr int D_TOTAL_F = D_ZTF + 128;      // ~169.5 KB

// one K-chunk (64) of 3xTF32 mma. warp tile = 32 rows x 64 cols.
__device__ __forceinline__ void mma_chunk(float (&c)[2][8][4], const float* sA, int ldA,
                                          const float* sB,
                                          int warpM, int warpN, int g, int tig) {
    #pragma unroll
    for (int kt = 0; kt < 8; kt++) {
        const int k0 = kt * 8;
        float ah[2][4], al[2][4];
        #pragma unroll
        for (int mt = 0; mt < 2; mt++) {
            const float* pr = sA + (warpM * 32 + mt * 16 + g) * ldA + k0 + tig;
            split_tf32(pr[0],            ah[mt][0], al[mt][0]);
            split_tf32(pr[8 * ldA],      ah[mt][1], al[mt][1]);
            split_tf32(pr[4],            ah[mt][2], al[mt][2]);
            split_tf32(pr[8 * ldA + 4],  ah[mt][3], al[mt][3]);
        }
        #pragma unroll
        for (int nt = 0; nt < 8; nt++) {
            int col = warpN * 64 + nt * 8 + g;
            float b0h, b0l, b1h, b1l;
            split_tf32(sB[(k0 + tig) * 136 + col],     b0h, b0l);
            split_tf32(sB[(k0 + tig + 4) * 136 + col], b1h, b1l);
            #pragma unroll
            for (int mt = 0; mt < 2; mt++) {
                mma_tf32(c[mt][nt], al[mt][0], al[mt][1], al[mt][2], al[mt][3], b0h, b1h);
                mma_tf32(c[mt][nt], ah[mt][0], ah[mt][1], ah[mt][2], ah[mt][3], b0l, b1l);
                mma_tf32(c[mt][nt], ah[mt][0], ah[mt][1], ah[mt][2], ah[mt][3], b0h, b1h);
            }
        }
    }
}

__device__ __forceinline__ void zero_c(float (&c)[2][8][4]) {
    #pragma unroll
    for (int mt = 0; mt < 2; mt++)
        #pragma unroll
        for (int nt = 0; nt < 8; nt++)
            #pragma unroll
            for (int i = 0; i < 4; i++) c[mt][nt][i] = 0.f;
}

__device__ __forceinline__ void stage_B(float* sB, const float* Wsrc, int tid) {
    #pragma unroll
    for (int idx = tid; idx < 64 * 32; idx += 256) {
        int k = idx >> 5, n4 = (idx & 31) << 2;
        float4 v = *reinterpret_cast<const float4*>(Wsrc + k * 128 + n4);
        *reinterpret_cast<float4*>(sB + k * 136 + n4) = v;
    }
}

// epilogue: x = scale_row * C + bias; store to buf; accumulate sum_{col>=1} x^2
// into s_ss (pre-zeroed) via 2 shfls + 1 atomic per row-fragment.
__device__ __forceinline__ void epilogue_x(const float (&c)[2][8][4], float* buf,
                                           const float* __restrict__ bias,
                                           const float* s_scale, float* s_ss,
                                           int warpM, int warpN, int g, int tig) {
    #pragma unroll
    for (int mt = 0; mt < 2; mt++) {
        int row = warpM * 32 + mt * 16 + g;
        float sc0 = s_scale[row], sc1 = s_scale[row + 8];
        float sq0 = 0.f, sq1 = 0.f;
        #pragma unroll
        for (int nt = 0; nt < 8; nt++) {
            int col = warpN * 64 + nt * 8 + tig * 2;
            float b0 = bias[col], b1 = bias[col + 1];
            float v00 = fmaf(sc0, c[mt][nt][0], b0);
            float v01 = fmaf(sc0, c[mt][nt][1], b1);
            float v10 = fmaf(sc1, c[mt][nt][2], b0);
            float v11 = fmaf(sc1, c[mt][nt][3], b1);
            buf[row * 132 + col]           = v00;
            buf[row * 132 + col + 1]       = v01;
            buf[(row + 8) * 132 + col]     = v10;
            buf[(row + 8) * 132 + col + 1] = v11;
            sq0 += (col == 0) ? 0.f : v00 * v00;
            sq0 += v01 * v01;
            sq1 += (col == 0) ? 0.f : v10 * v10;
            sq1 += v11 * v11;
        }
        sq0 += __shfl_xor_sync(0xffffffffu, sq0, 1);
        sq0 += __shfl_xor_sync(0xffffffffu, sq0, 2);
        sq1 += __shfl_xor_sync(0xffffffffu, sq1, 1);
        sq1 += __shfl_xor_sync(0xffffffffu, sq1, 2);
        if (tig == 0) {
            atomicAdd(&s_ss[row], sq0);
            atomicAdd(&s_ss[row + 8], sq1);
        }
    }
}

// ---------------- weight prep ----------------
__global__ void prep_weights(const float* __restrict__ lqW, const float* __restrict__ lkvW,
                             const float* __restrict__ wqW, const float* __restrict__ wkW,
                             const float* __restrict__ wvW) {
    int m = blockIdx.y;
    const float* W; float* O; int cols, colsPad; int shift;
    if (m == 0)      { W = lqW;  O = g_Wt_lq;  cols = QF;  colsPad = QFP;  shift = 1; }
    else if (m == 1) { W = lkvW; O = g_Wt_lkv; cols = KVF; colsPad = KVFP; shift = 1; }
    else if (m == 2) { W = wqW;  O = g_Wt_q;   cols = 128; colsPad = 128;  shift = 0; }
    else if (m == 3) { W = wkW;  O = g_Wt_k;   cols = 128; colsPad = 128;  shift = 0; }
    else             { W = wvW;  O = g_Wt_v;   cols = 128; colsPad = 128;  shift = 0; }
    int idx = blockIdx.x * blockDim.x + threadIdx.x;
    if (idx < colsPad * 128) {
        int k = idx >> 7, n = idx & 127;
        int ks = k + shift;
        O[idx] = (ks < cols) ? W[n * cols + ks] : 0.f;
    }
}

// ---------------- D kernel: fused node path ----------------
__global__ __launch_bounds__(256, 1) void d_kernel(
    const float* __restrict__ h, const float* __restrict__ te_b,
    const float* __restrict__ lq_b, const float* __restrict__ lq_s,
    const float* __restrict__ wq_b, const float* __restrict__ wq_s,
    const float* __restrict__ wk_b, const float* __restrict__ wk_s,
    const float* __restrict__ wv_b, const float* __restrict__ wv_s,
    const float* __restrict__ att) {
    extern __shared__ float sm[];
    float* s_act  = sm;
    float* s_q    = sm + D_Q;
    float* s_stage= sm + D_Q;          // aliases q
    float* s_bmat = sm + D_BMAT;
    float* s_ss   = sm + D_SS;
    float* s_s    = sm + D_S;
    float* s_t    = sm + D_T;
    float* s_sq   = sm + D_SQ;
    float* s_tq   = sm + D_TQ;
    float* s_w    = sm + D_W;
    float* s_ztf  = sm + D_ZTF;
    int tid = threadIdx.x, wid = tid >> 5, lane = tid & 31;
    int g = lane >> 2, tig = lane & 3;
    int warpM = wid >> 1, warpN = wid & 1;
    int d0 = blockIdx.x * 128;

    if (tid < 128) s_ztf[tid] = (tid < 100) ? cosf(te_b[tid]) : 0.f;

    int rr = tid >> 1, half = tid & 1;
    bool rvalid = (d0 + rr) < cD;
    float sqacc = 0.f;

    float c[2][8][4];
    // GEMM1: leaky(raw features, j-space) x shifted Wt_lq (K=256 padded)
    zero_c(c);
    for (int kc = 0; kc < 4; kc++) {
        __syncthreads();
        {
            int kkb = half * 32;
            #pragma unroll
            for (int f = 0; f < 8; f++) {
                int kk = kkb + f * 4;
                int j = kc * 64 + kk;
                float4 v = make_float4(0.f, 0.f, 0.f, 0.f);
                if (rvalid) {
                    if (j < 100)
                        v = *reinterpret_cast<const float4*>(h + (size_t)(d0 + rr) * 100 + j);
                    else if (j < 200)
                        v = *reinterpret_cast<const float4*>(s_ztf + (j - 100));
                }
                sqacc = fmaf(v.x, v.x, sqacc); sqacc = fmaf(v.y, v.y, sqacc);
                sqacc = fmaf(v.z, v.z, sqacc); sqacc = fmaf(v.w, v.w, sqacc);
                float4 l = make_float4(leaky(v.x), leaky(v.y), leaky(v.z), leaky(v.w));
                *reinterpret_cast<float4*>(s_stage + rr * 68 + kk) = l;
            }
        }
        stage_B(s_bmat, g_Wt_lq + kc * 64 * 128, tid);
        __syncthreads();
        mma_chunk(c, s_stage, 68, s_bmat, warpM, warpN, g, tig);
    }
    sqacc += __shfl_xor_sync(0xffffffffu, sqacc, 1);
    __syncthreads();
    if (half == 0) s_ss[rr] = sqacc;
    __syncthreads();
    // stats1: expmap scale
    if (tid < 128) {
        float n = sqrtf(fmaxf(s_ss[tid], 1e-8f));
        s_s[tid]  = sinhf(n) / n;
        s_ss[tid] = 0.f;
    }
    __syncthreads();
    epilogue_x(c, s_act, lq_b, s_s, s_ss, warpM, warpN, g, tig);   // act = x1 raw
    __syncthreads();
    // stats2: s1 (t1 unused; col0 has zero weights downstream)
    float esc1 = expf(*lq_s);
    if (tid < 128) {
        float x0 = s_act[tid * 132];
        float t  = esc1 / (1.f + expf(-x0)) + 1.1f;
        s_s[tid]  = sqrtf((t * t - 1.f) / fmaxf(s_ss[tid], 1e-8f));
        s_ss[tid] = 0.f;
    }
    __syncthreads();

    // GEMM wq: x1 -> x_q (scale s1 deferred into epilogue)
    zero_c(c);
    for (int kc = 0; kc < 2; kc++) {
        __syncthreads();
        stage_B(s_bmat, g_Wt_q + kc * 64 * 128, tid);
        __syncthreads();
        mma_chunk(c, s_act + kc * 64, 132, s_bmat, warpM, warpN, g, tig);
    }
    __syncthreads();
    epilogue_x(c, s_q, wq_b, s_s, s_ss, warpM, warpN, g, tig);     // q = x_q raw
    __syncthreads();
    float escq = expf(*wq_s);
    if (tid < 128) {
        float x0 = s_q[tid * 132];
        float t  = escq / (1.f + expf(-x0)) + 1.1f;
        s_tq[tid] = t;
        s_sq[tid] = sqrtf((t * t - 1.f) / fmaxf(s_ss[tid], 1e-8f));
        s_ss[tid] = 0.f;
    }
    __syncthreads();
    // store Qh (transformed) to global
    for (int idx = tid; idx < 128 * 32; idx += 256) {
        int r = idx >> 5, f = (idx & 31) << 2;
        if ((d0 + r) < cD) {
            float4 v = *reinterpret_cast<const float4*>(s_q + r * 132 + f);
            float s = s_sq[r];
            v.x *= s; v.y *= s; v.z *= s; v.w *= s;
            if (f == 0) v.x = s_tq[r];
            *reinterpret_cast<float4*>(g_QhD + (size_t)(d0 + r) * 128 + f) = v;
        }
    }

    // GEMM wk: x1 -> x_k (scale s1 = s_s still valid)
    zero_c(c);
    for (int kc = 0; kc < 2; kc++) {
        __syncthreads();
        stage_B(s_bmat, g_Wt_k + kc * 64 * 128, tid);
        __syncthreads();
        mma_chunk(c, s_act + kc * 64, 132, s_bmat, warpM, warpN, g, tig);
    }
    __syncthreads();
    epilogue_x(c, s_act, wk_b, s_s, s_ss, warpM, warpN, g, tig);   // act = x_k raw
    __syncthreads();
    float esck = expf(*wk_s);
    if (tid < 128) {
        float x0 = s_act[tid * 132];
        float t  = esck / (1.f + expf(-x0)) + 1.1f;
        s_t[tid]  = t;
        s_s[tid]  = sqrtf((t * t - 1.f) / fmaxf(s_ss[tid], 1e-8f));
        s_ss[tid] = 0.f;
    }
    __syncthreads();

    // self logits -> weights
    float attv = *att;
    for (int i = 0; i < 16; i++) {
        int r = wid * 16 + i;
        float sq = s_sq[r], sk = s_s[r];
        float inner = 0.f;
        #pragma unroll
        for (int cc = 0; cc < 4; cc++) {
            int col = lane + cc * 32;
            if (col > 0)
                inner = fmaf(sq * s_q[r * 132 + col], sk * s_act[r * 132 + col], inner);
        }
        inner = warp_reduce_sum(inner);
        if (lane == 0) {
            inner -= s_tq[r] * s_t[r];
            s_w[r] = expf((2.f + 2.f * inner) / attv);
        }
    }
    __syncthreads();

    // GEMM wv: x_k -> x_v (scale s_k = s_s); write into q (x_q dead)
    zero_c(c);
    for (int kc = 0; kc < 2; kc++) {
        __syncthreads();
        stage_B(s_bmat, g_Wt_v + kc * 64 * 128, tid);
        __syncthreads();
        mma_chunk(c, s_act + kc * 64, 132, s_bmat, warpM, warpN, g, tig);
    }
    __syncthreads();
    epilogue_x(c, s_q, wv_b, s_s, s_ss, warpM, warpN, g, tig);     // q = x_v raw
    __syncthreads();
    float escv = expf(*wv_s);
    if (tid < 128) {
        float x0 = s_q[tid * 132];
        float t  = escv / (1.f + expf(-x0)) + 1.1f;
        s_t[tid] = t;
        s_s[tid] = sqrtf((t * t - 1.f) / fmaxf(s_ss[tid], 1e-8f));
    }
    __syncthreads();

    // init acc/ssum with self term
    for (int i = 0; i < 16; i++) {
        int r = wid * 16 + i, d = d0 + r;
        if (d >= cD) continue;
        float wgt = s_w[r], s3 = s_s[r], t3 = s_t[r];
        #pragma unroll
        for (int cc = 0; cc < 4; cc++) {
            int col = lane + cc * 32;
            float v = (col == 0) ? t3 : s_q[r * 132 + col] * s3;
            g_acc[(size_t)d * 128 + col] = wgt * v;
        }
        if (lane == 0) g_ssum[d] = wgt;
    }
}

// ---------------- E kernel: fused edge path ----------------
__global__ __launch_bounds__(256, 2) void e_kernel(
    const float* __restrict__ h, const float* __restrict__ ef,
    const float* __restrict__ dt, const float* __restrict__ te_w,
    const float* __restrict__ te_b,
    const float* __restrict__ lkv_b, const float* __restrict__ lkv_s,
    const float* __restrict__ wk_b, const float* __restrict__ wk_s,
    const float* __restrict__ wv_b, const float* __restrict__ wv_s,
    const float* __restrict__ att, const int* __restrict__ edge_dst) {
    extern __shared__ float sm[];
    float* s_act  = sm;
    float* s_stage= sm;                 // aliases act
    float* s_bmat = sm + E_BMAT;
    float* s_ss   = sm + E_SS;
    float* s_s    = sm + E_S;
    float* s_t    = sm + E_T;
    float* s_w    = sm + E_W;
    int*   s_dst  = reinterpret_cast<int*>(sm + E_DST);
    float* s_dtv  = sm + E_DTV;
    int tid = threadIdx.x, wid = tid >> 5, lane = tid & 31;
    int g = lane >> 2, tig = lane & 3;
    int warpM = wid >> 1, warpN = wid & 1;
    int e0 = blockIdx.x * 128;

    if (tid < 128) {
        int e = e0 + tid;
        bool v = (e < cE);
        s_dst[tid] = v ? edge_dst[e] : -1;
        s_dtv[tid] = v ? dt[e] : 0.f;
    }
    __syncthreads();

    int rr = tid >> 1, half = tid & 1;
    bool rvalid = (e0 + rr) < cE;
    float dte = s_dtv[rr];
    float sqacc = 0.f;

    float c[2][8][4];
    // GEMM1: leaky(raw features, j-space) x shifted Wt_lkv (K=320, 5 chunks)
    zero_c(c);
    for (int kc = 0; kc < 5; kc++) {
        __syncthreads();
        {
            int kkb = half * 32;
            #pragma unroll
            for (int f = 0; f < 8; f++) {
                int kk = kkb + f * 4;
                int j = kc * 64 + kk;
                float4 v = make_float4(0.f, 0.f, 0.f, 0.f);
                if (rvalid) {
                    if (j < 100)
                        v = *reinterpret_cast<const float4*>(h + (size_t)(cD + e0 + rr) * 100 + j);
                    else if (j < 200)
                        v = *reinterpret_cast<const float4*>(ef + (size_t)(e0 + rr) * 100 + (j - 100));
                    else if (j < 300) {
                        int jj = j - 200;
                        float4 w4 = *reinterpret_cast<const float4*>(te_w + jj);
                        float4 b4 = *reinterpret_cast<const float4*>(te_b + jj);
                        v.x = fast_cos(fmaf(dte, w4.x, b4.x));
                        v.y = fast_cos(fmaf(dte, w4.y, b4.y));
                        v.z = fast_cos(fmaf(dte, w4.z, b4.z));
                        v.w = fast_cos(fmaf(dte, w4.w, b4.w));
                    }
                }
                sqacc = fmaf(v.x, v.x, sqacc); sqacc = fmaf(v.y, v.y, sqacc);
                sqacc = fmaf(v.z, v.z, sqacc); sqacc = fmaf(v.w, v.w, sqacc);
                float4 l = make_float4(leaky(v.x), leaky(v.y), leaky(v.z), leaky(v.w));
                *reinterpret_cast<float4*>(s_stage + rr * 68 + kk) = l;
            }
        }
        stage_B(s_bmat, g_Wt_lkv + kc * 64 * 128, tid);
        __syncthreads();
        mma_chunk(c, s_stage, 68, s_bmat, warpM, warpN, g, tig);
    }
    sqacc += __shfl_xor_sync(0xffffffffu, sqacc, 1);
    __syncthreads();
    if (half == 0) s_ss[rr] = sqacc;
    __syncthreads();
    if (tid < 128) {
        float n = sqrtf(fmaxf(s_ss[tid], 1e-8f));
        s_s[tid]  = sinhf(n) / n;
        s_ss[tid] = 0.f;
    }
    __syncthreads();
    epilogue_x(c, s_act, lkv_b, s_s, s_ss, warpM, warpN, g, tig);  // act = x1 raw
    __syncthreads();
    float esc1 = expf(*lkv_s);
    if (tid < 128) {
        float x0 = s_act[tid * 132];
        float t  = esc1 / (1.f + expf(-x0)) + 1.1f;
        s_s[tid]  = sqrtf((t * t - 1.f) / fmaxf(s_ss[tid], 1e-8f));
        s_ss[tid] = 0.f;
    }
    __syncthreads();

    // GEMM wk: x1 -> x_k
    zero_c(c);
    for (int kc = 0; kc < 2; kc++) {
        __syncthreads();
        stage_B(s_bmat, g_Wt_k + kc * 64 * 128, tid);
        __syncthreads();
        mma_chunk(c, s_act + kc * 64, 132, s_bmat, warpM, warpN, g, tig);
    }
    __syncthreads();
    epilogue_x(c, s_act, wk_b, s_s, s_ss, warpM, warpN, g, tig);   // act = x_k raw
    __syncthreads();
    float esck = expf(*wk_s);
    if (tid < 128) {
        float x0 = s_act[tid * 132];
        float t  = esck / (1.f + expf(-x0)) + 1.1f;
        s_t[tid]  = t;
        s_s[tid]  = sqrtf((t * t - 1.f) / fmaxf(s_ss[tid], 1e-8f));
        s_ss[tid] = 0.f;
    }
    __syncthreads();

    // logits + ssum atomics (Kh applied on the fly from raw x_k)
    float attv = *att;
    for (int i = 0; i < 16; i++) {
        int r = wid * 16 + i;
        int dv = s_dst[r];
        float inner = 0.f;
        float sk = s_s[r];
        if (dv >= 0) {
            #pragma unroll
            for (int cc = 0; cc < 4; cc++) {
                int col = lane + cc * 32;
                if (col > 0)
                    inner = fmaf(sk * s_act[r * 132 + col],
                                 g_QhD[(size_t)dv * 128 + col], inner);
            }
        }
        inner = warp_reduce_sum(inner);
        if (lane == 0 && dv >= 0) {
            inner -= s_t[r] * g_QhD[(size_t)dv * 128];
            float wgt = expf((2.f + 2.f * inner) / attv);
            s_w[r] = wgt;
            atomicAdd(&g_ssum[dv], wgt);
        }
    }
    __syncthreads();

    // GEMM wv: x_k -> x_v (scale s_k = s_s)
    zero_c(c);
    for (int kc = 0; kc < 2; kc++) {
        __syncthreads();
        stage_B(s_bmat, g_Wt_v + kc * 64 * 128, tid);
        __syncthreads();
        mma_chunk(c, s_act + kc * 64, 132, s_bmat, warpM, warpN, g, tig);
    }
    __syncthreads();
    epilogue_x(c, s_act, wv_b, s_s, s_ss, warpM, warpN, g, tig);   // act = x_v raw
    __syncthreads();
    float escv = expf(*wv_s);
    if (tid < 128) {
        float x0 = s_act[tid * 132];
        float t  = escv / (1.f + expf(-x0)) + 1.1f;
        s_t[tid] = t;
        s_s[tid] = sqrtf((t * t - 1.f) / fmaxf(s_ss[tid], 1e-8f));
    }
    __syncthreads();

    // weighted scatter
    for (int i = 0; i < 16; i++) {
        int r = wid * 16 + i;
        int dv = s_dst[r];
        if (dv < 0) continue;
        float wgt = s_w[r], s3 = s_s[r], t3 = s_t[r];
        #pragma unroll
        for (int cc = 0; cc < 4; cc++) {
            int col = lane + cc * 32;
            float v = (col == 0) ? t3 : s_act[r * 132 + col] * s3;
            atomicAdd(&g_acc[(size_t)dv * 128 + col], wgt * v);
        }
    }
}

// ---------------- finalize ----------------
__global__ void finalize_kernel(float* __restrict__ out) {
    int d = blockIdx.x * 4 + (threadIdx.x >> 5);
    int lane = threadIdx.x & 31;
    if (d >= cD) return;
    float inv_s = 1.f / g_ssum[d];
    float rv[4];
    float sq = 0.f;
    #pragma unroll
    for (int i = 0; i < 4; i++) {
        int c = lane + 32 * i;
        float v = g_acc[(size_t)d * 128 + c] * inv_s;
        rv[i] = v;
        if (c != 0) sq += v * v;
    }
    sq = warp_reduce_sum(sq);
    float r0 = __shfl_sync(0xffffffffu, rv[0], 0);
    float neg_inner = r0 * r0 - sq;
    float denom = sqrtf(fmaxf(fabsf(neg_inner), 1e-8f));
    float a = fmaxf(r0 / denom, 1.f + 1e-7f);
    float coef = acoshf(a) / sqrtf(fmaxf(a * a - 1.f, 1e-8f));
    #pragma unroll
    for (int i = 0; i < 4; i++) {
        int c = lane + 32 * i;
        out[(size_t)d * 128 + c] = (c == 0) ? 0.f : coef * (rv[i] / denom);
    }
}

// ---------------- launch ----------------
extern "C" void kernel_launch(void* const* d_in, const int* in_sizes, int n_in,
                              void* d_out, int out_size) {
    const float* h     = (const float*)d_in[0];
    const float* ef    = (const float*)d_in[1];
    const float* dt    = (const float*)d_in[2];
    const float* te_w  = (const float*)d_in[3];
    const float* te_b  = (const float*)d_in[4];
    const float* lq_W  = (const float*)d_in[5];
    const float* lq_b  = (const float*)d_in[6];
    const float* lq_s  = (const float*)d_in[7];
    const float* lkv_W = (const float*)d_in[8];
    const float* lkv_b = (const float*)d_in[9];
    const float* lkv_s = (const float*)d_in[10];
    const float* wq_W  = (const float*)d_in[11];
    const float* wq_b  = (const float*)d_in[12];
    const float* wq_s  = (const float*)d_in[13];
    const float* wk_W  = (const float*)d_in[14];
    const float* wk_b  = (const float*)d_in[15];
    const float* wk_s  = (const float*)d_in[16];
    const float* wv_W  = (const float*)d_in[17];
    const float* wv_b  = (const float*)d_in[18];
    const float* wv_s  = (const float*)d_in[19];
    const float* att   = (const float*)d_in[20];
    const int*   edst  = (const int*)d_in[21];
    float* out = (float*)d_out;

    cudaFuncSetAttribute(d_kernel, cudaFuncAttributeMaxDynamicSharedMemorySize,
                         D_TOTAL_F * 4);
    cudaFuncSetAttribute(e_kernel, cudaFuncAttributeMaxDynamicSharedMemorySize,
                         E_TOTAL_F * 4);

    prep_weights<<<dim3((KVFP * 128 + 255) / 256, 5), 256>>>(lq_W, lkv_W, wq_W, wk_W, wv_W);
    d_kernel<<<(cD + 127) / 128, 256, D_TOTAL_F * 4>>>(
        h, te_b, lq_b, lq_s, wq_b, wq_s, wk_b, wk_s, wv_b, wv_s, att);
    e_kernel<<<(cE + 127) / 128, 256, E_TOTAL_F * 4>>>(
        h, ef, dt, te_w, te_b, lkv_b, lkv_s, wk_b, wk_s, wv_b, wv_s, att, edst);
    finalize_kernel<<<(cD + 3) / 4, 128>>>(out);
}